// round 1
// baseline (speedup 1.0000x reference)
#include <cuda_runtime.h>

#define BSZ   4
#define TLEN  2048
#define DMODEL 1024
#define DHEAD 64
#define NROWS (BSZ*TLEN)

// Scratch (allocation-free rule: __device__ globals)
__device__ float g_Q[NROWS*DHEAD];
__device__ float g_K[NROWS*DHEAD];

// ----------------------------------------------------------------------------
// Projection: out[row][d] = sum_c x[row][c] * W[d][c]
// grid = (NROWS/64, 2) : y==0 -> W_Q -> g_Q ; y==1 -> W_K -> g_K
// block = 256 threads, 16x16 thread grid, 4x4 register tile each.
// ----------------------------------------------------------------------------
__global__ __launch_bounds__(256) void proj_kernel(
    const float* __restrict__ x,
    const float* __restrict__ Wq,
    const float* __restrict__ Wk)
{
    __shared__ float xs[64][64];   // [row][k]   row-major, float4-friendly
    __shared__ float wt[64][68];   // [k][dout]  transposed W chunk (pad 4)

    const float* W    = (blockIdx.y == 0) ? Wq : Wk;
    float*       outp = (blockIdx.y == 0) ? g_Q : g_K;

    const int tid = threadIdx.x;
    const int tx  = tid & 15;
    const int ty  = tid >> 4;
    const int row0 = blockIdx.x * 64;

    float acc[4][4] = {};

    for (int kc = 0; kc < DMODEL; kc += 64) {
        // x tile: 64 rows x 64 k   (coalesced float4 per 16 lanes/row)
        #pragma unroll
        for (int rr = 0; rr < 4; rr++) {
            int r = rr * 16 + ty;
            float4 v = *(const float4*)&x[(size_t)(row0 + r) * DMODEL + kc + tx * 4];
            *(float4*)&xs[r][tx * 4] = v;
        }
        // W tile: [64 dout][64 k], transpose into wt[k][dout]
        #pragma unroll
        for (int rr = 0; rr < 4; rr++) {
            int dout = rr * 16 + ty;
            float4 v = *(const float4*)&W[(size_t)dout * DMODEL + kc + tx * 4];
            wt[tx * 4 + 0][dout] = v.x;
            wt[tx * 4 + 1][dout] = v.y;
            wt[tx * 4 + 2][dout] = v.z;
            wt[tx * 4 + 3][dout] = v.w;
        }
        __syncthreads();

        #pragma unroll
        for (int k0 = 0; k0 < 64; k0 += 4) {
            float a[4][4];
            #pragma unroll
            for (int i = 0; i < 4; i++) {
                float4 t = *(const float4*)&xs[ty * 4 + i][k0];  // broadcast
                a[i][0] = t.x; a[i][1] = t.y; a[i][2] = t.z; a[i][3] = t.w;
            }
            #pragma unroll
            for (int kk = 0; kk < 4; kk++) {
                float4 t = *(const float4*)&wt[k0 + kk][tx * 4]; // contiguous
                float b0 = t.x, b1 = t.y, b2 = t.z, b3 = t.w;
                #pragma unroll
                for (int i = 0; i < 4; i++) {
                    acc[i][0] += a[i][kk] * b0;
                    acc[i][1] += a[i][kk] * b1;
                    acc[i][2] += a[i][kk] * b2;
                    acc[i][3] += a[i][kk] * b3;
                }
            }
        }
        __syncthreads();
    }

    #pragma unroll
    for (int i = 0; i < 4; i++) {
        float4 v = make_float4(acc[i][0], acc[i][1], acc[i][2], acc[i][3]);
        *(float4*)&outp[(size_t)(row0 + ty * 4 + i) * DHEAD + tx * 4] = v;
    }
}

// ----------------------------------------------------------------------------
// Flash attention, BM = BN = 64, online softmax. V == K (reference bug).
// grid = (TLEN/64, BSZ), block = 256 threads (16x16, 4x4 tile each).
// ----------------------------------------------------------------------------
__global__ __launch_bounds__(256) void attn_kernel(float* __restrict__ out)
{
    __shared__ float Qs [64][64];  // [qrow][d]        row-major
    __shared__ float Ksr[64][64];  // [krow][d]        row-major (for P@V)
    __shared__ float Ksd[64][68];  // [d][krow]        transposed (for Q@K^T)
    __shared__ float Ps [64][64];  // [qrow][krow]

    const int b   = blockIdx.y;
    const int qt  = blockIdx.x;
    const int tid = threadIdx.x;
    const int tx  = tid & 15;
    const int ty  = tid >> 4;

    const int qrow0 = b * TLEN + qt * 64;

    // Load Q tile
    #pragma unroll
    for (int rr = 0; rr < 4; rr++) {
        int r = rr * 16 + ty;
        *(float4*)&Qs[r][tx * 4] =
            *(const float4*)&g_Q[(size_t)(qrow0 + r) * DHEAD + tx * 4];
    }

    float o[4][4] = {};
    float mrow[4], lrow[4];
    #pragma unroll
    for (int i = 0; i < 4; i++) { mrow[i] = -1e30f; lrow[i] = 0.f; }
    const float scale = 0.03125f;  // 1/sqrt(1024)

    for (int kt = 0; kt <= qt; kt++) {
        const int krow0 = b * TLEN + kt * 64;
        #pragma unroll
        for (int rr = 0; rr < 4; rr++) {
            int r = rr * 16 + ty;
            float4 v = *(const float4*)&g_K[(size_t)(krow0 + r) * DHEAD + tx * 4];
            *(float4*)&Ksr[r][tx * 4] = v;
            Ksd[tx * 4 + 0][r] = v.x;
            Ksd[tx * 4 + 1][r] = v.y;
            Ksd[tx * 4 + 2][r] = v.z;
            Ksd[tx * 4 + 3][r] = v.w;
        }
        __syncthreads();

        // ---- S = Qs @ Ks^T  (4x4 per thread) ----
        float s[4][4] = {};
        #pragma unroll
        for (int d0 = 0; d0 < 64; d0 += 4) {
            float a[4][4];
            #pragma unroll
            for (int i = 0; i < 4; i++) {
                float4 t = *(const float4*)&Qs[ty * 4 + i][d0];   // broadcast
                a[i][0] = t.x; a[i][1] = t.y; a[i][2] = t.z; a[i][3] = t.w;
            }
            #pragma unroll
            for (int dd = 0; dd < 4; dd++) {
                float4 t = *(const float4*)&Ksd[d0 + dd][tx * 4]; // contiguous
                float b0 = t.x, b1 = t.y, b2 = t.z, b3 = t.w;
                #pragma unroll
                for (int i = 0; i < 4; i++) {
                    s[i][0] += a[i][dd] * b0;
                    s[i][1] += a[i][dd] * b1;
                    s[i][2] += a[i][dd] * b2;
                    s[i][3] += a[i][dd] * b3;
                }
            }
        }
        #pragma unroll
        for (int i = 0; i < 4; i++)
            #pragma unroll
            for (int j = 0; j < 4; j++)
                s[i][j] *= scale;

        if (kt == qt) {  // causal mask on the diagonal tile (uniform branch)
            #pragma unroll
            for (int i = 0; i < 4; i++)
                #pragma unroll
                for (int j = 0; j < 4; j++)
                    if (tx * 4 + j > ty * 4 + i) s[i][j] = -1e30f;
        }

        // ---- online softmax (per row, reduce across the 16 tx lanes) ----
        #pragma unroll
        for (int i = 0; i < 4; i++) {
            float tm = fmaxf(fmaxf(s[i][0], s[i][1]), fmaxf(s[i][2], s[i][3]));
            #pragma unroll
            for (int m = 1; m < 16; m <<= 1)
                tm = fmaxf(tm, __shfl_xor_sync(0xffffffffu, tm, m));
            float nm   = fmaxf(mrow[i], tm);
            float corr = __expf(mrow[i] - nm);
            mrow[i] = nm;
            float ps = 0.f;
            #pragma unroll
            for (int j = 0; j < 4; j++) {
                float p = __expf(s[i][j] - nm);
                s[i][j] = p;
                ps += p;
            }
            #pragma unroll
            for (int m = 1; m < 16; m <<= 1)
                ps += __shfl_xor_sync(0xffffffffu, ps, m);
            lrow[i] = lrow[i] * corr + ps;
            #pragma unroll
            for (int j = 0; j < 4; j++) o[i][j] *= corr;
            *(float4*)&Ps[ty * 4 + i][tx * 4] =
                make_float4(s[i][0], s[i][1], s[i][2], s[i][3]);
        }
        __syncthreads();

        // ---- O += P @ V   (V == Ksr) ----
        #pragma unroll
        for (int k0 = 0; k0 < 64; k0 += 4) {
            float a[4][4];
            #pragma unroll
            for (int i = 0; i < 4; i++) {
                float4 t = *(const float4*)&Ps[ty * 4 + i][k0];   // broadcast
                a[i][0] = t.x; a[i][1] = t.y; a[i][2] = t.z; a[i][3] = t.w;
            }
            #pragma unroll
            for (int kk = 0; kk < 4; kk++) {
                float4 t = *(const float4*)&Ksr[k0 + kk][tx * 4]; // contiguous
                float b0 = t.x, b1 = t.y, b2 = t.z, b3 = t.w;
                #pragma unroll
                for (int i = 0; i < 4; i++) {
                    o[i][0] += a[i][kk] * b0;
                    o[i][1] += a[i][kk] * b1;
                    o[i][2] += a[i][kk] * b2;
                    o[i][3] += a[i][kk] * b3;
                }
            }
        }
        __syncthreads();
    }

    // epilogue: divide by l, write out
    #pragma unroll
    for (int i = 0; i < 4; i++) {
        float inv = 1.0f / lrow[i];
        float4 v = make_float4(o[i][0] * inv, o[i][1] * inv,
                               o[i][2] * inv, o[i][3] * inv);
        *(float4*)&out[(size_t)(qrow0 + ty * 4 + i) * DHEAD + tx * 4] = v;
    }
}

extern "C" void kernel_launch(void* const* d_in, const int* in_sizes, int n_in,
                              void* d_out, int out_size)
{
    const float* x  = (const float*)d_in[0];
    const float* Wq = (const float*)d_in[1];
    const float* Wk = (const float*)d_in[2];
    // d_in[3] (W_V) intentionally unused: reference computes V with W_K.
    float* out = (float*)d_out;

    proj_kernel<<<dim3(NROWS / 64, 2), 256>>>(x, Wq, Wk);
    attn_kernel<<<dim3(TLEN / 64, BSZ), 256>>>(out);
}

// round 2
// speedup vs baseline: 2.1629x; 2.1629x over previous
#include <cuda_runtime.h>

#define BSZ    4
#define TLEN   2048
#define DMODEL 1024
#define DHEAD  64
#define NROWS  (BSZ*TLEN)

// Scratch (allocation-free rule: __device__ globals)
__device__ float g_Q[NROWS*DHEAD];
__device__ float g_K[NROWS*DHEAD];

// ---------------------------------------------------------------------------
// helpers
// ---------------------------------------------------------------------------
__device__ __forceinline__ unsigned f2tf(float a) {
    unsigned r;
    asm("cvt.rna.tf32.f32 %0, %1;" : "=r"(r) : "f"(a));
    return r;  // bits are a valid fp32 with low mantissa zeroed
}

__device__ __forceinline__ void mma_tf32(float c[4],
                                         unsigned a0, unsigned a1, unsigned a2, unsigned a3,
                                         unsigned b0, unsigned b1) {
    asm volatile(
        "mma.sync.aligned.m16n8k8.row.col.f32.tf32.tf32.f32 "
        "{%0,%1,%2,%3}, {%4,%5,%6,%7}, {%8,%9}, {%0,%1,%2,%3};"
        : "+f"(c[0]), "+f"(c[1]), "+f"(c[2]), "+f"(c[3])
        : "r"(a0), "r"(a1), "r"(a2), "r"(a3), "r"(b0), "r"(b1));
}

__device__ __forceinline__ unsigned fbits(float f) { return __float_as_uint(f); }

// ---------------------------------------------------------------------------
// Projection (3xTF32): out[row][d] = sum_c x[row][c] * W[d][c]
// grid = (NROWS/128, 2) ; y==0 -> W_Q -> g_Q ; y==1 -> W_K -> g_K
// block 256 = 8 warps: 4 m-warps (32 rows each) x 2 n-warps (32 cols each)
// ---------------------------------------------------------------------------
#define PBM 128
#define PBK 32
#define PPAD 4    // row stride 36 -> A/B fragment LDS conflict-free (4*gid+qd)

__global__ __launch_bounds__(256) void proj_mma(
    const float* __restrict__ x,
    const float* __restrict__ Wq,
    const float* __restrict__ Wk)
{
    __shared__ float xh[PBM][PBK+PPAD], xl[PBM][PBK+PPAD];
    __shared__ float wh[64][PBK+PPAD],  wl[64][PBK+PPAD];

    const float* W    = blockIdx.y ? Wk : Wq;
    float*       outp = blockIdx.y ? g_K : g_Q;

    const int tid  = threadIdx.x;
    const int lane = tid & 31;
    const int w    = tid >> 5;
    const int gid  = lane >> 2;
    const int qd   = lane & 3;
    const int mw   = w & 3;     // row-warp
    const int nw   = w >> 2;    // col-warp
    const int row0 = blockIdx.x * PBM;

    float acc[2][4][4] = {};    // [mtile][ntile][reg]

    float4 px[4], pw[2];
    // prefetch first tiles
    #pragma unroll
    for (int i = 0; i < 4; i++) {
        int id = tid + 256 * i;
        px[i] = *(const float4*)&x[(size_t)(row0 + (id >> 3)) * DMODEL + (id & 7) * 4];
    }
    #pragma unroll
    for (int i = 0; i < 2; i++) {
        int id = tid + 256 * i;
        pw[i] = *(const float4*)&W[(size_t)(id >> 3) * DMODEL + (id & 7) * 4];
    }

    for (int kc = 0; kc < DMODEL; kc += PBK) {
        __syncthreads();  // previous compute done (WAR on smem)
        // store prefetched tiles, hi/lo split
        #pragma unroll
        for (int i = 0; i < 4; i++) {
            int id = tid + 256 * i;
            int r = id >> 3, c = (id & 7) * 4;
            float v[4] = {px[i].x, px[i].y, px[i].z, px[i].w};
            float4 h4, l4;
            float* hp = &h4.x; float* lp = &l4.x;
            #pragma unroll
            for (int j = 0; j < 4; j++) {
                float hi = __uint_as_float(f2tf(v[j]));
                hp[j] = hi;
                lp[j] = __uint_as_float(f2tf(v[j] - hi));
            }
            *(float4*)&xh[r][c] = h4;
            *(float4*)&xl[r][c] = l4;
        }
        #pragma unroll
        for (int i = 0; i < 2; i++) {
            int id = tid + 256 * i;
            int r = id >> 3, c = (id & 7) * 4;
            float v[4] = {pw[i].x, pw[i].y, pw[i].z, pw[i].w};
            float4 h4, l4;
            float* hp = &h4.x; float* lp = &l4.x;
            #pragma unroll
            for (int j = 0; j < 4; j++) {
                float hi = __uint_as_float(f2tf(v[j]));
                hp[j] = hi;
                lp[j] = __uint_as_float(f2tf(v[j] - hi));
            }
            *(float4*)&wh[r][c] = h4;
            *(float4*)&wl[r][c] = l4;
        }
        // issue next prefetch (overlaps compute)
        if (kc + PBK < DMODEL) {
            #pragma unroll
            for (int i = 0; i < 4; i++) {
                int id = tid + 256 * i;
                px[i] = *(const float4*)&x[(size_t)(row0 + (id >> 3)) * DMODEL + kc + PBK + (id & 7) * 4];
            }
            #pragma unroll
            for (int i = 0; i < 2; i++) {
                int id = tid + 256 * i;
                pw[i] = *(const float4*)&W[(size_t)(id >> 3) * DMODEL + kc + PBK + (id & 7) * 4];
            }
        }
        __syncthreads();  // tiles visible

        #pragma unroll
        for (int k8 = 0; k8 < PBK / 8; k8++) {
            unsigned ah[2][4], al[2][4];
            #pragma unroll
            for (int mt = 0; mt < 2; mt++) {
                int r = mw * 32 + mt * 16 + gid;
                int c = k8 * 8 + qd;
                ah[mt][0] = fbits(xh[r][c]);     al[mt][0] = fbits(xl[r][c]);
                ah[mt][1] = fbits(xh[r+8][c]);   al[mt][1] = fbits(xl[r+8][c]);
                ah[mt][2] = fbits(xh[r][c+4]);   al[mt][2] = fbits(xl[r][c+4]);
                ah[mt][3] = fbits(xh[r+8][c+4]); al[mt][3] = fbits(xl[r+8][c+4]);
            }
            #pragma unroll
            for (int nt = 0; nt < 4; nt++) {
                int n = nw * 32 + nt * 8 + gid;
                int c = k8 * 8 + qd;
                unsigned bh0 = fbits(wh[n][c]), bh1 = fbits(wh[n][c+4]);
                unsigned bl0 = fbits(wl[n][c]), bl1 = fbits(wl[n][c+4]);
                #pragma unroll
                for (int mt = 0; mt < 2; mt++) {
                    mma_tf32(acc[mt][nt], ah[mt][0], ah[mt][1], ah[mt][2], ah[mt][3], bh0, bh1);
                    mma_tf32(acc[mt][nt], al[mt][0], al[mt][1], al[mt][2], al[mt][3], bh0, bh1);
                    mma_tf32(acc[mt][nt], ah[mt][0], ah[mt][1], ah[mt][2], ah[mt][3], bl0, bl1);
                }
            }
        }
    }

    // epilogue
    #pragma unroll
    for (int mt = 0; mt < 2; mt++) {
        int r = row0 + mw * 32 + mt * 16 + gid;
        #pragma unroll
        for (int nt = 0; nt < 4; nt++) {
            int c = nw * 32 + nt * 8 + 2 * qd;
            *(float2*)&outp[(size_t)r * DHEAD + c] =
                make_float2(acc[mt][nt][0], acc[mt][nt][1]);
            *(float2*)&outp[(size_t)(r + 8) * DHEAD + c] =
                make_float2(acc[mt][nt][2], acc[mt][nt][3]);
        }
    }
}

// ---------------------------------------------------------------------------
// Flash attention, tf32 MMA. BM=BN=64, online softmax. V == K (reference bug).
// grid = (TLEN/64, BSZ), block 256 = 8 warps: (mw = w&3) rows, (nc = w>>2) cols
// ---------------------------------------------------------------------------
__global__ __launch_bounds__(256) void attn_mma(float* __restrict__ out)
{
    __shared__ float Ks[2][64][68];           // double-buffered K tile (tf32-rounded)
    __shared__ float Ps[64][68];              // P tile (tf32-rounded)
    __shared__ float m_s[64];
    __shared__ float pmax[2][64], psum[2][64];
    __shared__ float l_s[64];

    const int b   = blockIdx.y;
    const int qt  = blockIdx.x;
    const int tid = threadIdx.x;
    const int lane = tid & 31;
    const int w    = tid >> 5;
    const int gid  = lane >> 2;
    const int qd   = lane & 3;
    const int mw   = w & 3;
    const int nc   = w >> 2;

    const int qrow0 = b * TLEN + qt * 64;
    const int r0l   = mw * 16 + gid;           // local row (and r0l+8)

    // Q fragments: 16x64, held in registers for the whole kernel (tf32-rounded)
    unsigned aq[8][4];
    {
        const float* qp = &g_Q[(size_t)(qrow0 + r0l) * DHEAD];
        #pragma unroll
        for (int k8 = 0; k8 < 8; k8++) {
            int c = k8 * 8 + qd;
            aq[k8][0] = f2tf(qp[c]);
            aq[k8][1] = f2tf(qp[8 * DHEAD + c]);
            aq[k8][2] = f2tf(qp[c + 4]);
            aq[k8][3] = f2tf(qp[8 * DHEAD + c + 4]);
        }
    }

    if (tid < 64) { m_s[tid] = -1e30f; l_s[tid] = 0.f; }

    float o[4][4] = {};
    float lr0 = 0.f, lr1 = 0.f;   // running l, kept redundantly in nc==0 warps

    // prefetch tile 0 and store
    float4 pre[4];
    {
        const int krow0 = b * TLEN;  // kt = 0
        #pragma unroll
        for (int i = 0; i < 4; i++) {
            int id = tid + 256 * i;
            pre[i] = *(const float4*)&g_K[(size_t)(krow0 + (id >> 4)) * DHEAD + (id & 15) * 4];
        }
        #pragma unroll
        for (int i = 0; i < 4; i++) {
            int id = tid + 256 * i;
            int r = id >> 4, c = (id & 15) * 4;
            float v[4] = {pre[i].x, pre[i].y, pre[i].z, pre[i].w};
            float4 t;
            t.x = __uint_as_float(f2tf(v[0]));
            t.y = __uint_as_float(f2tf(v[1]));
            t.z = __uint_as_float(f2tf(v[2]));
            t.w = __uint_as_float(f2tf(v[3]));
            *(float4*)&Ks[0][r][c] = t;
        }
    }

    const float scale = 0.03125f;  // 1/sqrt(d_model=1024)

    for (int kt = 0; kt <= qt; kt++) {
        const int cur = kt & 1;
        __syncthreads();   // sync_top: Ks[cur] visible; prev PV done (Ps/pmax free)

        // issue prefetch of next tile (overlaps S + softmax)
        if (kt < qt) {
            const int krow0 = b * TLEN + (kt + 1) * 64;
            #pragma unroll
            for (int i = 0; i < 4; i++) {
                int id = tid + 256 * i;
                pre[i] = *(const float4*)&g_K[(size_t)(krow0 + (id >> 4)) * DHEAD + (id & 15) * 4];
            }
        }

        // ---- S = Q @ K^T ----
        float s[4][4] = {};
        #pragma unroll
        for (int k8 = 0; k8 < 8; k8++) {
            int c = k8 * 8 + qd;
            #pragma unroll
            for (int nt = 0; nt < 4; nt++) {
                int n = nc * 32 + nt * 8 + gid;
                unsigned b0 = fbits(Ks[cur][n][c]);
                unsigned b1 = fbits(Ks[cur][n][c + 4]);
                mma_tf32(s[nt], aq[k8][0], aq[k8][1], aq[k8][2], aq[k8][3], b0, b1);
            }
        }
        #pragma unroll
        for (int nt = 0; nt < 4; nt++)
            #pragma unroll
            for (int j = 0; j < 4; j++)
                s[nt][j] *= scale;

        if (kt == qt) {  // causal mask on diagonal tile
            #pragma unroll
            for (int nt = 0; nt < 4; nt++) {
                int cb = nc * 32 + nt * 8 + 2 * qd;
                if (cb     > r0l)     s[nt][0] = -1e30f;
                if (cb + 1 > r0l)     s[nt][1] = -1e30f;
                if (cb     > r0l + 8) s[nt][2] = -1e30f;
                if (cb + 1 > r0l + 8) s[nt][3] = -1e30f;
            }
        }

        // ---- local row max over this warp's 32 cols ----
        float tm0 = -1e30f, tm1 = -1e30f;
        #pragma unroll
        for (int nt = 0; nt < 4; nt++) {
            tm0 = fmaxf(tm0, fmaxf(s[nt][0], s[nt][1]));
            tm1 = fmaxf(tm1, fmaxf(s[nt][2], s[nt][3]));
        }
        tm0 = fmaxf(tm0, __shfl_xor_sync(0xffffffffu, tm0, 1));
        tm0 = fmaxf(tm0, __shfl_xor_sync(0xffffffffu, tm0, 2));
        tm1 = fmaxf(tm1, __shfl_xor_sync(0xffffffffu, tm1, 1));
        tm1 = fmaxf(tm1, __shfl_xor_sync(0xffffffffu, tm1, 2));
        pmax[nc][r0l]     = tm0;
        pmax[nc][r0l + 8] = tm1;

        __syncthreads();   // sync1: pmax ready

        float mo0 = m_s[r0l], mo1 = m_s[r0l + 8];
        float mn0 = fmaxf(mo0, fmaxf(pmax[0][r0l],     pmax[1][r0l]));
        float mn1 = fmaxf(mo1, fmaxf(pmax[0][r0l + 8], pmax[1][r0l + 8]));
        float corr0 = __expf(mo0 - mn0);
        float corr1 = __expf(mo1 - mn1);

        float ps0 = 0.f, ps1 = 0.f;
        #pragma unroll
        for (int nt = 0; nt < 4; nt++) {
            float p0 = __expf(s[nt][0] - mn0);
            float p1 = __expf(s[nt][1] - mn0);
            float p2 = __expf(s[nt][2] - mn1);
            float p3 = __expf(s[nt][3] - mn1);
            ps0 += p0 + p1;
            ps1 += p2 + p3;
            int cb = nc * 32 + nt * 8 + 2 * qd;
            *(float2*)&Ps[r0l][cb] =
                make_float2(__uint_as_float(f2tf(p0)), __uint_as_float(f2tf(p1)));
            *(float2*)&Ps[r0l + 8][cb] =
                make_float2(__uint_as_float(f2tf(p2)), __uint_as_float(f2tf(p3)));
        }
        ps0 += __shfl_xor_sync(0xffffffffu, ps0, 1);
        ps0 += __shfl_xor_sync(0xffffffffu, ps0, 2);
        ps1 += __shfl_xor_sync(0xffffffffu, ps1, 1);
        ps1 += __shfl_xor_sync(0xffffffffu, ps1, 2);
        psum[nc][r0l]     = ps0;
        psum[nc][r0l + 8] = ps1;

        // rescale O accumulators
        #pragma unroll
        for (int nt = 0; nt < 4; nt++) {
            o[nt][0] *= corr0; o[nt][1] *= corr0;
            o[nt][2] *= corr1; o[nt][3] *= corr1;
        }

        // store next K tile (tf32-rounded) into the other buffer
        if (kt < qt) {
            #pragma unroll
            for (int i = 0; i < 4; i++) {
                int id = tid + 256 * i;
                int r = id >> 4, c = (id & 15) * 4;
                float v[4] = {pre[i].x, pre[i].y, pre[i].z, pre[i].w};
                float4 t;
                t.x = __uint_as_float(f2tf(v[0]));
                t.y = __uint_as_float(f2tf(v[1]));
                t.z = __uint_as_float(f2tf(v[2]));
                t.w = __uint_as_float(f2tf(v[3]));
                *(float4*)&Ks[cur ^ 1][r][c] = t;
            }
        }

        __syncthreads();   // sync2: psum/Ps/next-Ks ready

        // l update + m_s update (nc==0 warps; all 4 quad lanes write same value)
        if (nc == 0) {
            lr0 = lr0 * corr0 + psum[0][r0l]     + psum[1][r0l];
            lr1 = lr1 * corr1 + psum[0][r0l + 8] + psum[1][r0l + 8];
            m_s[r0l]     = mn0;
            m_s[r0l + 8] = mn1;
        }

        // ---- O += P @ V  (V == K tile) ----
        #pragma unroll
        for (int k8 = 0; k8 < 8; k8++) {
            int c = k8 * 8 + qd;
            unsigned a0 = fbits(Ps[r0l][c]);
            unsigned a1 = fbits(Ps[r0l + 8][c]);
            unsigned a2 = fbits(Ps[r0l][c + 4]);
            unsigned a3 = fbits(Ps[r0l + 8][c + 4]);
            #pragma unroll
            for (int nt = 0; nt < 4; nt++) {
                int d = nc * 32 + nt * 8 + gid;
                unsigned b0 = fbits(Ks[cur][k8 * 8 + qd][d]);
                unsigned b1 = fbits(Ks[cur][k8 * 8 + qd + 4][d]);
                mma_tf32(o[nt], a0, a1, a2, a3, b0, b1);
            }
        }
    }

    // publish l, then epilogue
    if (nc == 0) { l_s[r0l] = lr0; l_s[r0l + 8] = lr1; }
    __syncthreads();

    float inv0 = 1.0f / l_s[r0l];
    float inv1 = 1.0f / l_s[r0l + 8];
    #pragma unroll
    for (int nt = 0; nt < 4; nt++) {
        int c = nc * 32 + nt * 8 + 2 * qd;
        *(float2*)&out[(size_t)(qrow0 + r0l) * DHEAD + c] =
            make_float2(o[nt][0] * inv0, o[nt][1] * inv0);
        *(float2*)&out[(size_t)(qrow0 + r0l + 8) * DHEAD + c] =
            make_float2(o[nt][2] * inv1, o[nt][3] * inv1);
    }
}

extern "C" void kernel_launch(void* const* d_in, const int* in_sizes, int n_in,
                              void* d_out, int out_size)
{
    const float* x  = (const float*)d_in[0];
    const float* Wq = (const float*)d_in[1];
    const float* Wk = (const float*)d_in[2];
    // d_in[3] (W_V) intentionally unused: reference computes V with W_K.
    float* out = (float*)d_out;

    proj_mma<<<dim3(NROWS / PBM, 2), 256>>>(x, Wq, Wk);
    attn_mma<<<dim3(TLEN / 64, BSZ), 256>>>(out);
}

// round 3
// speedup vs baseline: 2.2466x; 1.0387x over previous
#include <cuda_runtime.h>

#define BSZ    4
#define TLEN   2048
#define DMODEL 1024
#define DHEAD  64
#define NROWS  (BSZ*TLEN)

// Scratch (allocation-free rule: __device__ globals)
__device__ float  g_Q[NROWS*DHEAD];
__device__ float  g_K[NROWS*DHEAD];
// Packed W fragments: [k8g(128)][n(128)][qd(4)] -> {Wh[c], Wh[c+4], Wl[c], Wl[c+4]}, c = k8g*8+qd
__device__ float4 g_Wp[128*128*4];

// ---------------------------------------------------------------------------
// helpers
// ---------------------------------------------------------------------------
__device__ __forceinline__ unsigned f2tf(float a) {
    unsigned r;
    asm("cvt.rna.tf32.f32 %0, %1;" : "=r"(r) : "f"(a));
    return r;
}
__device__ __forceinline__ float trunc_tf(float a) {   // tf32 truncation (what MMA HW does)
    return __uint_as_float(__float_as_uint(a) & 0xffffe000u);
}
__device__ __forceinline__ unsigned fbits(float f) { return __float_as_uint(f); }

__device__ __forceinline__ void mma_tf32(float c[4],
                                         unsigned a0, unsigned a1, unsigned a2, unsigned a3,
                                         unsigned b0, unsigned b1) {
    asm volatile(
        "mma.sync.aligned.m16n8k8.row.col.f32.tf32.tf32.f32 "
        "{%0,%1,%2,%3}, {%4,%5,%6,%7}, {%8,%9}, {%0,%1,%2,%3};"
        : "+f"(c[0]), "+f"(c[1]), "+f"(c[2]), "+f"(c[3])
        : "r"(a0), "r"(a1), "r"(a2), "r"(a3), "r"(b0), "r"(b1));
}

// ---------------------------------------------------------------------------
// Prep: split W_Q|W_K (stacked as 128 rows) into hi/lo tf32 fragment-packed layout.
// grid 256 x 256 threads, one float4 each.
// ---------------------------------------------------------------------------
__global__ __launch_bounds__(256) void prep_w(
    const float* __restrict__ Wq, const float* __restrict__ Wk)
{
    int idx  = blockIdx.x * 256 + threadIdx.x;     // [0, 128*128*4)
    int k8g  = idx >> 9;
    int rem  = idx & 511;
    int n    = rem >> 2;
    int qd   = rem & 3;
    int c    = k8g * 8 + qd;
    const float* src = (n < 64) ? (Wq + (size_t)n * DMODEL)
                                : (Wk + (size_t)(n - 64) * DMODEL);
    float w0 = src[c], w1 = src[c + 4];
    float h0 = trunc_tf(w0), h1 = trunc_tf(w1);
    g_Wp[idx] = make_float4(h0, h1, w0 - h0, w1 - h1);
}

// ---------------------------------------------------------------------------
// Projection (3xTF32 via trunc-split): [Q|K] = x @ [Wq|Wk]^T
// BM=32, BN=128, grid = 256 CTAs (2/SM). 8 warps: 2 m-warps x 4 n-warps.
// ---------------------------------------------------------------------------
__global__ __launch_bounds__(256, 2) void proj_mma(const float* __restrict__ x)
{
    __shared__ float4 Bs[4 * 128 * 4];          // [k8l][n][qd]  32 KB
    __shared__ float  Xh[32][36], Xl[32][36];

    const int tid  = threadIdx.x;
    const int lane = tid & 31;
    const int w    = tid >> 5;
    const int gid  = lane >> 2;
    const int qd   = lane & 3;
    const int mw   = w & 1;
    const int nw   = w >> 1;
    const int row0 = blockIdx.x * 32;

    const int xr = tid >> 3, xc = (tid & 7) * 4;

    float acc[4][4] = {};

    // prologue: prefetch chunk 0
    float4 px = *(const float4*)&x[(size_t)(row0 + xr) * DMODEL + xc];
    float4 pb[8];
    #pragma unroll
    for (int i = 0; i < 8; i++) pb[i] = g_Wp[tid + 256 * i];

    for (int kc = 0; kc < DMODEL; kc += 32) {
        __syncthreads();   // WAR: previous MMA phase done with Bs / Xh / Xl

        // store x tile (hi/lo trunc split)
        {
            float v[4] = {px.x, px.y, px.z, px.w};
            float4 h4, l4; float* hp = &h4.x; float* lp = &l4.x;
            #pragma unroll
            for (int j = 0; j < 4; j++) { hp[j] = trunc_tf(v[j]); lp[j] = v[j] - hp[j]; }
            *(float4*)&Xh[xr][xc] = h4;
            *(float4*)&Xl[xr][xc] = l4;
        }
        // store W tile
        #pragma unroll
        for (int i = 0; i < 8; i++) Bs[tid + 256 * i] = pb[i];

        // prefetch next chunk (wrap to 0 on last iter; harmless, keeps code uniform)
        int kn = (kc + 32 < DMODEL) ? kc + 32 : 0;
        px = *(const float4*)&x[(size_t)(row0 + xr) * DMODEL + kn + xc];
        {
            int base = (kn >> 3) * 512;
            #pragma unroll
            for (int i = 0; i < 8; i++) pb[i] = g_Wp[base + tid + 256 * i];
        }
        __syncthreads();   // tiles visible

        #pragma unroll
        for (int k8 = 0; k8 < 4; k8++) {
            const int r = mw * 16 + gid, c = k8 * 8 + qd;
            unsigned ah0 = fbits(Xh[r][c]),     ah1 = fbits(Xh[r+8][c]);
            unsigned ah2 = fbits(Xh[r][c+4]),   ah3 = fbits(Xh[r+8][c+4]);
            unsigned al0 = fbits(Xl[r][c]),     al1 = fbits(Xl[r+8][c]);
            unsigned al2 = fbits(Xl[r][c+4]),   al3 = fbits(Xl[r+8][c+4]);
            #pragma unroll
            for (int nt = 0; nt < 4; nt++) {
                int n = nw * 32 + nt * 8 + gid;
                float4 bv = Bs[(k8 * 128 + n) * 4 + qd];
                unsigned bh0 = fbits(bv.x), bh1 = fbits(bv.y);
                unsigned bl0 = fbits(bv.z), bl1 = fbits(bv.w);
                mma_tf32(acc[nt], ah0, ah1, ah2, ah3, bh0, bh1);
                mma_tf32(acc[nt], al0, al1, al2, al3, bh0, bh1);
                mma_tf32(acc[nt], ah0, ah1, ah2, ah3, bl0, bl1);
            }
        }
    }

    // epilogue: nw 0,1 -> Q cols 0..63 ; nw 2,3 -> K cols 0..63
    float* outp = (nw < 2) ? g_Q : g_K;
    const int r = row0 + mw * 16 + gid;
    #pragma unroll
    for (int nt = 0; nt < 4; nt++) {
        int cb = (nw & 1) * 32 + nt * 8 + 2 * qd;
        *(float2*)&outp[(size_t)r * DHEAD + cb] =
            make_float2(acc[nt][0], acc[nt][1]);
        *(float2*)&outp[(size_t)(r + 8) * DHEAD + cb] =
            make_float2(acc[nt][2], acc[nt][3]);
    }
}

// ---------------------------------------------------------------------------
// Flash attention, tf32 MMA. BM=32, BN=64, paired query tiles for balance.
// grid = (32 pairs, BSZ); CTA ph=0 -> qtile p, ph=1 -> qtile 63-p  (33 tiles total)
// 8 warps: mw = w&1 (16 rows), nc = w>>1 (16 cols). V == K (reference bug).
// ---------------------------------------------------------------------------
__global__ __launch_bounds__(256) void attn_mma(float* __restrict__ out)
{
    __shared__ float Ks[2][64][68];
    __shared__ float Ps[32][68];
    __shared__ float m_s[32], l_s[32];
    __shared__ float pmax[4][32], psum[4][32];

    const int b    = blockIdx.y;
    const int p    = blockIdx.x;
    const int tid  = threadIdx.x;
    const int lane = tid & 31;
    const int w    = tid >> 5;
    const int gid  = lane >> 2;
    const int qd   = lane & 3;
    const int mw   = w & 1;
    const int nc   = w >> 1;
    const int r0l  = mw * 16 + gid;

    const float scale = 0.03125f;   // 1/sqrt(d_model=1024)

    #pragma unroll 1
    for (int ph = 0; ph < 2; ph++) {
        const int q     = ph ? (63 - p) : p;
        const int nkv   = (q + 2) >> 1;          // ceil((q+1)/2)
        const int qrow0 = b * TLEN + q * 32;

        __syncthreads();   // previous phase fully done with smem
        if (tid < 32) { m_s[tid] = -1e30f; l_s[tid] = 0.f; }

        // Q fragments, held in registers for the whole phase
        unsigned aq[8][4];
        {
            const float* qp = &g_Q[(size_t)(qrow0 + r0l) * DHEAD];
            #pragma unroll
            for (int k8 = 0; k8 < 8; k8++) {
                int c = k8 * 8 + qd;
                aq[k8][0] = f2tf(qp[c]);
                aq[k8][1] = f2tf(qp[8 * DHEAD + c]);
                aq[k8][2] = f2tf(qp[c + 4]);
                aq[k8][3] = f2tf(qp[8 * DHEAD + c + 4]);
            }
        }

        float o[2][4] = {};
        float lr0 = 0.f, lr1 = 0.f;

        // prefetch + store kv tile 0
        float4 pre[4];
        {
            const int krow0 = b * TLEN;
            #pragma unroll
            for (int i = 0; i < 4; i++) {
                int id = tid + 256 * i;
                pre[i] = *(const float4*)&g_K[(size_t)(krow0 + (id >> 4)) * DHEAD + (id & 15) * 4];
            }
            #pragma unroll
            for (int i = 0; i < 4; i++) {
                int id = tid + 256 * i;
                float v[4] = {pre[i].x, pre[i].y, pre[i].z, pre[i].w};
                float4 t;
                t.x = __uint_as_float(f2tf(v[0]));
                t.y = __uint_as_float(f2tf(v[1]));
                t.z = __uint_as_float(f2tf(v[2]));
                t.w = __uint_as_float(f2tf(v[3]));
                *(float4*)&Ks[0][id >> 4][(id & 15) * 4] = t;
            }
        }

        #pragma unroll 1
        for (int kt = 0; kt < nkv; kt++) {
            const int cur = kt & 1;
            __syncthreads();   // Ks[cur] visible; prev PV done (Ps/pmax free)

            if (kt + 1 < nkv) {
                const int krow0 = b * TLEN + (kt + 1) * 64;
                #pragma unroll
                for (int i = 0; i < 4; i++) {
                    int id = tid + 256 * i;
                    pre[i] = *(const float4*)&g_K[(size_t)(krow0 + (id >> 4)) * DHEAD + (id & 15) * 4];
                }
            }

            // ---- S = Q @ K^T ----
            float s[2][4] = {};
            #pragma unroll
            for (int k8 = 0; k8 < 8; k8++) {
                int c = k8 * 8 + qd;
                #pragma unroll
                for (int nt = 0; nt < 2; nt++) {
                    int n = nc * 16 + nt * 8 + gid;
                    unsigned b0 = fbits(Ks[cur][n][c]);
                    unsigned b1 = fbits(Ks[cur][n][c + 4]);
                    mma_tf32(s[nt], aq[k8][0], aq[k8][1], aq[k8][2], aq[k8][3], b0, b1);
                }
            }
            #pragma unroll
            for (int nt = 0; nt < 2; nt++)
                #pragma unroll
                for (int j = 0; j < 4; j++)
                    s[nt][j] *= scale;

            if (kt == nkv - 1) {   // causal mask (only last tile can cross diagonal)
                #pragma unroll
                for (int nt = 0; nt < 2; nt++) {
                    int cb = kt * 64 + nc * 16 + nt * 8 + 2 * qd;
                    int ra = q * 32 + r0l, rb = ra + 8;
                    if (cb     > ra) s[nt][0] = -1e30f;
                    if (cb + 1 > ra) s[nt][1] = -1e30f;
                    if (cb     > rb) s[nt][2] = -1e30f;
                    if (cb + 1 > rb) s[nt][3] = -1e30f;
                }
            }

            // ---- warp-local row max (16 cols) ----
            float tm0 = fmaxf(fmaxf(s[0][0], s[0][1]), fmaxf(s[1][0], s[1][1]));
            float tm1 = fmaxf(fmaxf(s[0][2], s[0][3]), fmaxf(s[1][2], s[1][3]));
            tm0 = fmaxf(tm0, __shfl_xor_sync(0xffffffffu, tm0, 1));
            tm0 = fmaxf(tm0, __shfl_xor_sync(0xffffffffu, tm0, 2));
            tm1 = fmaxf(tm1, __shfl_xor_sync(0xffffffffu, tm1, 1));
            tm1 = fmaxf(tm1, __shfl_xor_sync(0xffffffffu, tm1, 2));
            pmax[nc][r0l]     = tm0;
            pmax[nc][r0l + 8] = tm1;

            __syncthreads();   // pmax ready

            float mo0 = m_s[r0l], mo1 = m_s[r0l + 8];
            float mn0 = fmaxf(fmaxf(fmaxf(pmax[0][r0l],     pmax[1][r0l]),
                                    fmaxf(pmax[2][r0l],     pmax[3][r0l])),     mo0);
            float mn1 = fmaxf(fmaxf(fmaxf(pmax[0][r0l + 8], pmax[1][r0l + 8]),
                                    fmaxf(pmax[2][r0l + 8], pmax[3][r0l + 8])), mo1);
            float corr0 = __expf(mo0 - mn0);
            float corr1 = __expf(mo1 - mn1);

            float ps0 = 0.f, ps1 = 0.f;
            #pragma unroll
            for (int nt = 0; nt < 2; nt++) {
                float p0 = __expf(s[nt][0] - mn0);
                float p1 = __expf(s[nt][1] - mn0);
                float p2 = __expf(s[nt][2] - mn1);
                float p3 = __expf(s[nt][3] - mn1);
                ps0 += p0 + p1;
                ps1 += p2 + p3;
                int cb = nc * 16 + nt * 8 + 2 * qd;
                *(float2*)&Ps[r0l][cb] =
                    make_float2(__uint_as_float(f2tf(p0)), __uint_as_float(f2tf(p1)));
                *(float2*)&Ps[r0l + 8][cb] =
                    make_float2(__uint_as_float(f2tf(p2)), __uint_as_float(f2tf(p3)));
            }
            ps0 += __shfl_xor_sync(0xffffffffu, ps0, 1);
            ps0 += __shfl_xor_sync(0xffffffffu, ps0, 2);
            ps1 += __shfl_xor_sync(0xffffffffu, ps1, 1);
            ps1 += __shfl_xor_sync(0xffffffffu, ps1, 2);
            psum[nc][r0l]     = ps0;
            psum[nc][r0l + 8] = ps1;

            #pragma unroll
            for (int nt = 0; nt < 2; nt++) {
                o[nt][0] *= corr0; o[nt][1] *= corr0;
                o[nt][2] *= corr1; o[nt][3] *= corr1;
            }

            // store next K tile into the other buffer
            if (kt + 1 < nkv) {
                #pragma unroll
                for (int i = 0; i < 4; i++) {
                    int id = tid + 256 * i;
                    float v[4] = {pre[i].x, pre[i].y, pre[i].z, pre[i].w};
                    float4 t;
                    t.x = __uint_as_float(f2tf(v[0]));
                    t.y = __uint_as_float(f2tf(v[1]));
                    t.z = __uint_as_float(f2tf(v[2]));
                    t.w = __uint_as_float(f2tf(v[3]));
                    *(float4*)&Ks[cur ^ 1][id >> 4][(id & 15) * 4] = t;
                }
            }

            __syncthreads();   // psum / Ps / next-Ks ready

            if (nc == 0) {
                lr0 = lr0 * corr0 + psum[0][r0l]     + psum[1][r0l]
                                  + psum[2][r0l]     + psum[3][r0l];
                lr1 = lr1 * corr1 + psum[0][r0l + 8] + psum[1][r0l + 8]
                                  + psum[2][r0l + 8] + psum[3][r0l + 8];
                m_s[r0l]     = mn0;
                m_s[r0l + 8] = mn1;
            }

            // ---- O += P @ V  (V == K tile) ----
            #pragma unroll
            for (int k8 = 0; k8 < 8; k8++) {
                int c = k8 * 8 + qd;
                unsigned a0 = fbits(Ps[r0l][c]);
                unsigned a1 = fbits(Ps[r0l + 8][c]);
                unsigned a2 = fbits(Ps[r0l][c + 4]);
                unsigned a3 = fbits(Ps[r0l + 8][c + 4]);
                #pragma unroll
                for (int nt = 0; nt < 2; nt++) {
                    int d = nc * 16 + nt * 8 + gid;
                    unsigned b0 = fbits(Ks[cur][c][d]);
                    unsigned b1 = fbits(Ks[cur][c + 4][d]);
                    mma_tf32(o[nt], a0, a1, a2, a3, b0, b1);
                }
            }
        }

        if (nc == 0) { l_s[r0l] = lr0; l_s[r0l + 8] = lr1; }
        __syncthreads();

        float inv0 = 1.0f / l_s[r0l];
        float inv1 = 1.0f / l_s[r0l + 8];
        #pragma unroll
        for (int nt = 0; nt < 2; nt++) {
            int cb = nc * 16 + nt * 8 + 2 * qd;
            *(float2*)&out[(size_t)(qrow0 + r0l) * DHEAD + cb] =
                make_float2(o[nt][0] * inv0, o[nt][1] * inv0);
            *(float2*)&out[(size_t)(qrow0 + r0l + 8) * DHEAD + cb] =
                make_float2(o[nt][2] * inv1, o[nt][3] * inv1);
        }
    }
}

extern "C" void kernel_launch(void* const* d_in, const int* in_sizes, int n_in,
                              void* d_out, int out_size)
{
    const float* x  = (const float*)d_in[0];
    const float* Wq = (const float*)d_in[1];
    const float* Wk = (const float*)d_in[2];
    // d_in[3] (W_V) intentionally unused: reference computes V with W_K.
    float* out = (float*)d_out;

    prep_w  <<<256, 256>>>(Wq, Wk);
    proj_mma<<<256, 256>>>(x);
    attn_mma<<<dim3(32, BSZ), 256>>>(out);
}

// round 4
// speedup vs baseline: 2.2473x; 1.0003x over previous
#include <cuda_runtime.h>

#define BSZ    4
#define TLEN   2048
#define DMODEL 1024
#define DHEAD  64
#define NROWS  (BSZ*TLEN)

// Scratch (allocation-free rule: __device__ globals)
__device__ float  g_Q[NROWS*DHEAD];
__device__ float  g_K[NROWS*DHEAD];
// Packed W fragments: [k8g(128)][n(128)][qd(4)] -> {Wh[c], Wh[c+4], Wl[c], Wl[c+4]}, c = k8g*8+qd
__device__ float4 g_Wp[128*128*4];

// ---------------------------------------------------------------------------
// helpers
// ---------------------------------------------------------------------------
__device__ __forceinline__ unsigned f2tf(float a) {
    unsigned r;
    asm("cvt.rna.tf32.f32 %0, %1;" : "=r"(r) : "f"(a));
    return r;
}
__device__ __forceinline__ float trunc_tf(float a) {   // tf32 truncation (what MMA HW does)
    return __uint_as_float(__float_as_uint(a) & 0xffffe000u);
}
__device__ __forceinline__ unsigned fbits(float f) { return __float_as_uint(f); }

__device__ __forceinline__ void mma_tf32(float c[4],
                                         unsigned a0, unsigned a1, unsigned a2, unsigned a3,
                                         unsigned b0, unsigned b1) {
    asm volatile(
        "mma.sync.aligned.m16n8k8.row.col.f32.tf32.tf32.f32 "
        "{%0,%1,%2,%3}, {%4,%5,%6,%7}, {%8,%9}, {%0,%1,%2,%3};"
        : "+f"(c[0]), "+f"(c[1]), "+f"(c[2]), "+f"(c[3])
        : "r"(a0), "r"(a1), "r"(a2), "r"(a3), "r"(b0), "r"(b1));
}

// ---------------------------------------------------------------------------
// Prep: split W_Q|W_K (stacked as 128 rows) into hi/lo tf32 fragment-packed layout.
// grid 256 x 256 threads, one float4 each.
// ---------------------------------------------------------------------------
__global__ __launch_bounds__(256) void prep_w(
    const float* __restrict__ Wq, const float* __restrict__ Wk)
{
    int idx  = blockIdx.x * 256 + threadIdx.x;     // [0, 128*128*4)
    int k8g  = idx >> 9;
    int rem  = idx & 511;
    int n    = rem >> 2;
    int qd   = rem & 3;
    int c    = k8g * 8 + qd;
    const float* src = (n < 64) ? (Wq + (size_t)n * DMODEL)
                                : (Wk + (size_t)(n - 64) * DMODEL);
    float w0 = src[c], w1 = src[c + 4];
    float h0 = trunc_tf(w0), h1 = trunc_tf(w1);
    g_Wp[idx] = make_float4(h0, h1, w0 - h0, w1 - h1);
}

// ---------------------------------------------------------------------------
// Projection (3xTF32 via trunc-split): [Q|K] = x @ [Wq|Wk]^T
// BM=32, BN=128, grid = 256 CTAs (2/SM). 8 warps: 2 m-warps x 4 n-warps.
// ---------------------------------------------------------------------------
__global__ __launch_bounds__(256, 2) void proj_mma(const float* __restrict__ x)
{
    __shared__ float4 Bs[4 * 128 * 4];          // [k8l][n][qd]  32 KB
    __shared__ float  Xh[32][36], Xl[32][36];

    const int tid  = threadIdx.x;
    const int lane = tid & 31;
    const int w    = tid >> 5;
    const int gid  = lane >> 2;
    const int qd   = lane & 3;
    const int mw   = w & 1;
    const int nw   = w >> 1;
    const int row0 = blockIdx.x * 32;

    const int xr = tid >> 3, xc = (tid & 7) * 4;

    float acc[4][4] = {};

    // prologue: prefetch chunk 0
    float4 px = *(const float4*)&x[(size_t)(row0 + xr) * DMODEL + xc];
    float4 pb[8];
    #pragma unroll
    for (int i = 0; i < 8; i++) pb[i] = g_Wp[tid + 256 * i];

    for (int kc = 0; kc < DMODEL; kc += 32) {
        __syncthreads();   // WAR: previous MMA phase done with Bs / Xh / Xl

        // store x tile (hi/lo trunc split)
        {
            float v[4] = {px.x, px.y, px.z, px.w};
            float4 h4, l4; float* hp = &h4.x; float* lp = &l4.x;
            #pragma unroll
            for (int j = 0; j < 4; j++) { hp[j] = trunc_tf(v[j]); lp[j] = v[j] - hp[j]; }
            *(float4*)&Xh[xr][xc] = h4;
            *(float4*)&Xl[xr][xc] = l4;
        }
        // store W tile
        #pragma unroll
        for (int i = 0; i < 8; i++) Bs[tid + 256 * i] = pb[i];

        // prefetch next chunk (wrap to 0 on last iter; harmless, keeps code uniform)
        int kn = (kc + 32 < DMODEL) ? kc + 32 : 0;
        px = *(const float4*)&x[(size_t)(row0 + xr) * DMODEL + kn + xc];
        {
            int base = (kn >> 3) * 512;
            #pragma unroll
            for (int i = 0; i < 8; i++) pb[i] = g_Wp[base + tid + 256 * i];
        }
        __syncthreads();   // tiles visible

        #pragma unroll
        for (int k8 = 0; k8 < 4; k8++) {
            const int r = mw * 16 + gid, c = k8 * 8 + qd;
            unsigned ah0 = fbits(Xh[r][c]),     ah1 = fbits(Xh[r+8][c]);
            unsigned ah2 = fbits(Xh[r][c+4]),   ah3 = fbits(Xh[r+8][c+4]);
            unsigned al0 = fbits(Xl[r][c]),     al1 = fbits(Xl[r+8][c]);
            unsigned al2 = fbits(Xl[r][c+4]),   al3 = fbits(Xl[r+8][c+4]);
            #pragma unroll
            for (int nt = 0; nt < 4; nt++) {
                int n = nw * 32 + nt * 8 + gid;
                float4 bv = Bs[(k8 * 128 + n) * 4 + qd];
                unsigned bh0 = fbits(bv.x), bh1 = fbits(bv.y);
                unsigned bl0 = fbits(bv.z), bl1 = fbits(bv.w);
                mma_tf32(acc[nt], ah0, ah1, ah2, ah3, bh0, bh1);
                mma_tf32(acc[nt], al0, al1, al2, al3, bh0, bh1);
                mma_tf32(acc[nt], ah0, ah1, ah2, ah3, bl0, bl1);
            }
        }
    }

    // epilogue: nw 0,1 -> Q cols 0..63 ; nw 2,3 -> K cols 0..63
    float* outp = (nw < 2) ? g_Q : g_K;
    const int r = row0 + mw * 16 + gid;
    #pragma unroll
    for (int nt = 0; nt < 4; nt++) {
        int cb = (nw & 1) * 32 + nt * 8 + 2 * qd;
        *(float2*)&outp[(size_t)r * DHEAD + cb] =
            make_float2(acc[nt][0], acc[nt][1]);
        *(float2*)&outp[(size_t)(r + 8) * DHEAD + cb] =
            make_float2(acc[nt][2], acc[nt][3]);
    }
}

// ---------------------------------------------------------------------------
// Flash attention, tf32 MMA. BM=32, BN=64, paired query tiles for balance.
// grid = (32 pairs, BSZ); CTA ph=0 -> qtile p, ph=1 -> qtile 63-p  (33 tiles total)
// 8 warps: mw = w&1 (16 rows), nc = w>>1 (16 cols). V == K (reference bug).
// ---------------------------------------------------------------------------
__global__ __launch_bounds__(256) void attn_mma(float* __restrict__ out)
{
    __shared__ float Ks[2][64][68];
    __shared__ float Ps[32][68];
    __shared__ float m_s[32], l_s[32];
    __shared__ float pmax[4][32], psum[4][32];

    const int b    = blockIdx.y;
    const int p    = blockIdx.x;
    const int tid  = threadIdx.x;
    const int lane = tid & 31;
    const int w    = tid >> 5;
    const int gid  = lane >> 2;
    const int qd   = lane & 3;
    const int mw   = w & 1;
    const int nc   = w >> 1;
    const int r0l  = mw * 16 + gid;

    const float scale = 0.03125f;   // 1/sqrt(d_model=1024)

    #pragma unroll 1
    for (int ph = 0; ph < 2; ph++) {
        const int q     = ph ? (63 - p) : p;
        const int nkv   = (q + 2) >> 1;          // ceil((q+1)/2)
        const int qrow0 = b * TLEN + q * 32;

        __syncthreads();   // previous phase fully done with smem
        if (tid < 32) { m_s[tid] = -1e30f; l_s[tid] = 0.f; }

        // Q fragments, held in registers for the whole phase
        unsigned aq[8][4];
        {
            const float* qp = &g_Q[(size_t)(qrow0 + r0l) * DHEAD];
            #pragma unroll
            for (int k8 = 0; k8 < 8; k8++) {
                int c = k8 * 8 + qd;
                aq[k8][0] = f2tf(qp[c]);
                aq[k8][1] = f2tf(qp[8 * DHEAD + c]);
                aq[k8][2] = f2tf(qp[c + 4]);
                aq[k8][3] = f2tf(qp[8 * DHEAD + c + 4]);
            }
        }

        float o[2][4] = {};
        float lr0 = 0.f, lr1 = 0.f;

        // prefetch + store kv tile 0
        float4 pre[4];
        {
            const int krow0 = b * TLEN;
            #pragma unroll
            for (int i = 0; i < 4; i++) {
                int id = tid + 256 * i;
                pre[i] = *(const float4*)&g_K[(size_t)(krow0 + (id >> 4)) * DHEAD + (id & 15) * 4];
            }
            #pragma unroll
            for (int i = 0; i < 4; i++) {
                int id = tid + 256 * i;
                float v[4] = {pre[i].x, pre[i].y, pre[i].z, pre[i].w};
                float4 t;
                t.x = __uint_as_float(f2tf(v[0]));
                t.y = __uint_as_float(f2tf(v[1]));
                t.z = __uint_as_float(f2tf(v[2]));
                t.w = __uint_as_float(f2tf(v[3]));
                *(float4*)&Ks[0][id >> 4][(id & 15) * 4] = t;
            }
        }

        #pragma unroll 1
        for (int kt = 0; kt < nkv; kt++) {
            const int cur = kt & 1;
            __syncthreads();   // Ks[cur] visible; prev PV done (Ps/pmax free)

            if (kt + 1 < nkv) {
                const int krow0 = b * TLEN + (kt + 1) * 64;
                #pragma unroll
                for (int i = 0; i < 4; i++) {
                    int id = tid + 256 * i;
                    pre[i] = *(const float4*)&g_K[(size_t)(krow0 + (id >> 4)) * DHEAD + (id & 15) * 4];
                }
            }

            // ---- S = Q @ K^T ----
            float s[2][4] = {};
            #pragma unroll
            for (int k8 = 0; k8 < 8; k8++) {
                int c = k8 * 8 + qd;
                #pragma unroll
                for (int nt = 0; nt < 2; nt++) {
                    int n = nc * 16 + nt * 8 + gid;
                    unsigned b0 = fbits(Ks[cur][n][c]);
                    unsigned b1 = fbits(Ks[cur][n][c + 4]);
                    mma_tf32(s[nt], aq[k8][0], aq[k8][1], aq[k8][2], aq[k8][3], b0, b1);
                }
            }
            #pragma unroll
            for (int nt = 0; nt < 2; nt++)
                #pragma unroll
                for (int j = 0; j < 4; j++)
                    s[nt][j] *= scale;

            if (kt == nkv - 1) {   // causal mask (only last tile can cross diagonal)
                #pragma unroll
                for (int nt = 0; nt < 2; nt++) {
                    int cb = kt * 64 + nc * 16 + nt * 8 + 2 * qd;
                    int ra = q * 32 + r0l, rb = ra + 8;
                    if (cb     > ra) s[nt][0] = -1e30f;
                    if (cb + 1 > ra) s[nt][1] = -1e30f;
                    if (cb     > rb) s[nt][2] = -1e30f;
                    if (cb + 1 > rb) s[nt][3] = -1e30f;
                }
            }

            // ---- warp-local row max (16 cols) ----
            float tm0 = fmaxf(fmaxf(s[0][0], s[0][1]), fmaxf(s[1][0], s[1][1]));
            float tm1 = fmaxf(fmaxf(s[0][2], s[0][3]), fmaxf(s[1][2], s[1][3]));
            tm0 = fmaxf(tm0, __shfl_xor_sync(0xffffffffu, tm0, 1));
            tm0 = fmaxf(tm0, __shfl_xor_sync(0xffffffffu, tm0, 2));
            tm1 = fmaxf(tm1, __shfl_xor_sync(0xffffffffu, tm1, 1));
            tm1 = fmaxf(tm1, __shfl_xor_sync(0xffffffffu, tm1, 2));
            pmax[nc][r0l]     = tm0;
            pmax[nc][r0l + 8] = tm1;

            __syncthreads();   // pmax ready

            float mo0 = m_s[r0l], mo1 = m_s[r0l + 8];
            float mn0 = fmaxf(fmaxf(fmaxf(pmax[0][r0l],     pmax[1][r0l]),
                                    fmaxf(pmax[2][r0l],     pmax[3][r0l])),     mo0);
            float mn1 = fmaxf(fmaxf(fmaxf(pmax[0][r0l + 8], pmax[1][r0l + 8]),
                                    fmaxf(pmax[2][r0l + 8], pmax[3][r0l + 8])), mo1);
            float corr0 = __expf(mo0 - mn0);
            float corr1 = __expf(mo1 - mn1);

            float ps0 = 0.f, ps1 = 0.f;
            #pragma unroll
            for (int nt = 0; nt < 2; nt++) {
                float p0 = __expf(s[nt][0] - mn0);
                float p1 = __expf(s[nt][1] - mn0);
                float p2 = __expf(s[nt][2] - mn1);
                float p3 = __expf(s[nt][3] - mn1);
                ps0 += p0 + p1;
                ps1 += p2 + p3;
                int cb = nc * 16 + nt * 8 + 2 * qd;
                *(float2*)&Ps[r0l][cb] =
                    make_float2(__uint_as_float(f2tf(p0)), __uint_as_float(f2tf(p1)));
                *(float2*)&Ps[r0l + 8][cb] =
                    make_float2(__uint_as_float(f2tf(p2)), __uint_as_float(f2tf(p3)));
            }
            ps0 += __shfl_xor_sync(0xffffffffu, ps0, 1);
            ps0 += __shfl_xor_sync(0xffffffffu, ps0, 2);
            ps1 += __shfl_xor_sync(0xffffffffu, ps1, 1);
            ps1 += __shfl_xor_sync(0xffffffffu, ps1, 2);
            psum[nc][r0l]     = ps0;
            psum[nc][r0l + 8] = ps1;

            #pragma unroll
            for (int nt = 0; nt < 2; nt++) {
                o[nt][0] *= corr0; o[nt][1] *= corr0;
                o[nt][2] *= corr1; o[nt][3] *= corr1;
            }

            // store next K tile into the other buffer
            if (kt + 1 < nkv) {
                #pragma unroll
                for (int i = 0; i < 4; i++) {
                    int id = tid + 256 * i;
                    float v[4] = {pre[i].x, pre[i].y, pre[i].z, pre[i].w};
                    float4 t;
                    t.x = __uint_as_float(f2tf(v[0]));
                    t.y = __uint_as_float(f2tf(v[1]));
                    t.z = __uint_as_float(f2tf(v[2]));
                    t.w = __uint_as_float(f2tf(v[3]));
                    *(float4*)&Ks[cur ^ 1][id >> 4][(id & 15) * 4] = t;
                }
            }

            __syncthreads();   // psum / Ps / next-Ks ready

            if (nc == 0) {
                lr0 = lr0 * corr0 + psum[0][r0l]     + psum[1][r0l]
                                  + psum[2][r0l]     + psum[3][r0l];
                lr1 = lr1 * corr1 + psum[0][r0l + 8] + psum[1][r0l + 8]
                                  + psum[2][r0l + 8] + psum[3][r0l + 8];
                m_s[r0l]     = mn0;
                m_s[r0l + 8] = mn1;
            }

            // ---- O += P @ V  (V == K tile) ----
            #pragma unroll
            for (int k8 = 0; k8 < 8; k8++) {
                int c = k8 * 8 + qd;
                unsigned a0 = fbits(Ps[r0l][c]);
                unsigned a1 = fbits(Ps[r0l + 8][c]);
                unsigned a2 = fbits(Ps[r0l][c + 4]);
                unsigned a3 = fbits(Ps[r0l + 8][c + 4]);
                #pragma unroll
                for (int nt = 0; nt < 2; nt++) {
                    int d = nc * 16 + nt * 8 + gid;
                    unsigned b0 = fbits(Ks[cur][c][d]);
                    unsigned b1 = fbits(Ks[cur][c + 4][d]);
                    mma_tf32(o[nt], a0, a1, a2, a3, b0, b1);
                }
            }
        }

        if (nc == 0) { l_s[r0l] = lr0; l_s[r0l + 8] = lr1; }
        __syncthreads();

        float inv0 = 1.0f / l_s[r0l];
        float inv1 = 1.0f / l_s[r0l + 8];
        #pragma unroll
        for (int nt = 0; nt < 2; nt++) {
            int cb = nc * 16 + nt * 8 + 2 * qd;
            *(float2*)&out[(size_t)(qrow0 + r0l) * DHEAD + cb] =
                make_float2(o[nt][0] * inv0, o[nt][1] * inv0);
            *(float2*)&out[(size_t)(qrow0 + r0l + 8) * DHEAD + cb] =
                make_float2(o[nt][2] * inv1, o[nt][3] * inv1);
        }
    }
}

extern "C" void kernel_launch(void* const* d_in, const int* in_sizes, int n_in,
                              void* d_out, int out_size)
{
    const float* x  = (const float*)d_in[0];
    const float* Wq = (const float*)d_in[1];
    const float* Wk = (const float*)d_in[2];
    // d_in[3] (W_V) intentionally unused: reference computes V with W_K.
    float* out = (float*)d_out;

    prep_w  <<<256, 256>>>(Wq, Wk);
    proj_mma<<<256, 256>>>(x);
    attn_mma<<<dim3(32, BSZ), 256>>>(out);
}

// round 5
// speedup vs baseline: 2.6526x; 1.1803x over previous
#include <cuda_runtime.h>
#include <cstdint>

#define BSZ    4
#define TLEN   2048
#define DMODEL 1024
#define DHEAD  64
#define NROWS  (BSZ*TLEN)

// Scratch (allocation-free rule: __device__ globals)
__device__ float g_Q[NROWS*DHEAD];
__device__ float g_K[NROWS*DHEAD];
// split-KV partials: [b][qt(32)][chunk(4)][64 rows][64 cols], plus per-row m,l
__device__ float g_part[4*32*4*64*64];
__device__ float g_pm[4*32*4*64];
__device__ float g_pl[4*32*4*64];

// ---------------------------------------------------------------------------
// helpers
// ---------------------------------------------------------------------------
__device__ __forceinline__ unsigned f2tf(float a) {
    unsigned r;
    asm("cvt.rna.tf32.f32 %0, %1;" : "=r"(r) : "f"(a));
    return r;
}
__device__ __forceinline__ unsigned fbits(float f) { return __float_as_uint(f); }

__device__ __forceinline__ void mma_tf32(float c[4],
                                         unsigned a0, unsigned a1, unsigned a2, unsigned a3,
                                         unsigned b0, unsigned b1) {
    asm volatile(
        "mma.sync.aligned.m16n8k8.row.col.f32.tf32.tf32.f32 "
        "{%0,%1,%2,%3}, {%4,%5,%6,%7}, {%8,%9}, {%0,%1,%2,%3};"
        : "+f"(c[0]), "+f"(c[1]), "+f"(c[2]), "+f"(c[3])
        : "r"(a0), "r"(a1), "r"(a2), "r"(a3), "r"(b0), "r"(b1));
}

__device__ __forceinline__ void cp16(uint32_t dst, const void* src) {
    asm volatile("cp.async.cg.shared.global [%0], [%1], 16;" :: "r"(dst), "l"(src));
}
__device__ __forceinline__ void cpcommit() {
    asm volatile("cp.async.commit_group;");
}
template<int N> __device__ __forceinline__ void cpwait() {
    asm volatile("cp.async.wait_group %0;" :: "n"(N));
}

// ---------------------------------------------------------------------------
// Projection (single tf32): out[row][d] = sum_c x[row][c] * W[d][c]
// grid = (128, 2): y==0 -> W_Q -> g_Q ; y==1 -> W_K -> g_K.  BM=64, BN=64.
// block 256 = 8 warps: 4 m-warps (16 rows) x 2 n-warps (32 cols).
// ---------------------------------------------------------------------------
__global__ __launch_bounds__(256) void proj_mma(
    const float* __restrict__ x,
    const float* __restrict__ Wq,
    const float* __restrict__ Wk)
{
    __shared__ float Xs[64][36];
    __shared__ float Ws[64][36];

    const float* W    = blockIdx.y ? Wk : Wq;
    float*       outp = blockIdx.y ? g_K : g_Q;

    const int tid  = threadIdx.x;
    const int lane = tid & 31;
    const int w    = tid >> 5;
    const int gid  = lane >> 2;
    const int qd   = lane & 3;
    const int mw   = w & 3;
    const int nw   = w >> 2;
    const int row0 = blockIdx.x * 64;

    float acc[4][4] = {};

    // per-thread load slots: 2 float4 per tile (512 float4 / 256 thr)
    float4 px[2], pw[2];
    #pragma unroll
    for (int i = 0; i < 2; i++) {
        int lin = tid + 256 * i;
        int r = lin >> 3, sg = (lin & 7) * 4;
        px[i] = *(const float4*)&x[(size_t)(row0 + r) * DMODEL + sg];
        pw[i] = *(const float4*)&W[(size_t)r * DMODEL + sg];
    }

    for (int kc = 0; kc < DMODEL; kc += 32) {
        __syncthreads();   // WAR: previous MMA phase done with Xs/Ws
        #pragma unroll
        for (int i = 0; i < 2; i++) {
            int lin = tid + 256 * i;
            int r = lin >> 3, sg = (lin & 7) * 4;
            float vx[4] = {px[i].x, px[i].y, px[i].z, px[i].w};
            float vw[4] = {pw[i].x, pw[i].y, pw[i].z, pw[i].w};
            #pragma unroll
            for (int j = 0; j < 4; j++) {
                Xs[r][sg + j] = __uint_as_float(f2tf(vx[j]));
                Ws[r][sg + j] = __uint_as_float(f2tf(vw[j]));
            }
        }
        // prefetch next chunk (wrap on last iter; harmless, keeps code uniform)
        int kn = (kc + 32 < DMODEL) ? kc + 32 : 0;
        #pragma unroll
        for (int i = 0; i < 2; i++) {
            int lin = tid + 256 * i;
            int r = lin >> 3, sg = (lin & 7) * 4;
            px[i] = *(const float4*)&x[(size_t)(row0 + r) * DMODEL + kn + sg];
            pw[i] = *(const float4*)&W[(size_t)r * DMODEL + kn + sg];
        }
        __syncthreads();   // tiles visible

        #pragma unroll
        for (int k8 = 0; k8 < 4; k8++) {
            const int r = mw * 16 + gid, c = k8 * 8 + qd;
            unsigned a0 = fbits(Xs[r][c]),     a1 = fbits(Xs[r + 8][c]);
            unsigned a2 = fbits(Xs[r][c + 4]), a3 = fbits(Xs[r + 8][c + 4]);
            #pragma unroll
            for (int nt = 0; nt < 4; nt++) {
                int n = nw * 32 + nt * 8 + gid;
                unsigned b0 = fbits(Ws[n][c]), b1 = fbits(Ws[n][c + 4]);
                mma_tf32(acc[nt], a0, a1, a2, a3, b0, b1);
            }
        }
    }

    const int r = row0 + mw * 16 + gid;
    #pragma unroll
    for (int nt = 0; nt < 4; nt++) {
        int cb = nw * 32 + nt * 8 + 2 * qd;
        *(float2*)&outp[(size_t)r * DHEAD + cb] =
            make_float2(acc[nt][0], acc[nt][1]);
        *(float2*)&outp[(size_t)(r + 8) * DHEAD + cb] =
            make_float2(acc[nt][2], acc[nt][3]);
    }
}

// ---------------------------------------------------------------------------
// Flash attention, split-KV. BM=64, BN=64. 4 warps, each owns 16 full rows ->
// softmax is entirely warp-local (no cross-warp smem, no softmax barriers).
// grid = (80 chunks, BSZ). Chunk decode: qt band t = qt/8 has t+1 chunks.
// V == K (reference bug). Partials (O,m,l) to scratch when nch > 1.
// ---------------------------------------------------------------------------
__global__ __launch_bounds__(128, 3) void attn_mma(float* __restrict__ out)
{
    __shared__ float Ks[2][64][68];
    __shared__ float Ps[64][68];

    const int b   = blockIdx.y;
    const int cid = blockIdx.x;

    // decode (qt, ck): band starts 0,8,24,48
    const int t     = (cid >= 48) ? 3 : (cid >= 24) ? 2 : (cid >= 8) ? 1 : 0;
    const int strt  = (t == 3) ? 48 : (t == 2) ? 24 : (t == 1) ? 8 : 0;
    const int rem   = cid - strt;
    const int qt    = 8 * t + rem / (t + 1);
    const int ck    = rem % (t + 1);
    const int ntile = qt + 1;
    const int nch   = t + 1;
    const int bse   = ntile / nch;
    const int ext   = ntile % nch;
    const int nkv   = bse + (ck < ext ? 1 : 0);
    const int kv0   = ck * bse + (ck < ext ? ck : ext);

    const int tid  = threadIdx.x;
    const int lane = tid & 31;
    const int w    = tid >> 5;
    const int gid  = lane >> 2;
    const int qd   = lane & 3;
    const int r0l  = w * 16 + gid;

    const int qrow0 = b * TLEN + qt * 64;
    const uint32_t ks_u32 = (uint32_t)__cvta_generic_to_shared(&Ks[0][0][0]);

    // --- cp.async K-tile issue (16B x 8 per thread = 16KB tile) ---
    auto issue_tile = [&](int buf, int ktg) {
        const float* kb = &g_K[(size_t)(b * TLEN + ktg * 64) * DHEAD];
        #pragma unroll
        for (int i = 0; i < 8; i++) {
            int lin = i * 128 + tid;
            int row = lin >> 4, sg = (lin & 15) * 4;
            cp16(ks_u32 + (uint32_t)(((buf * 64 + row) * 68 + sg) * 4),
                 kb + row * 64 + sg);
        }
        cpcommit();
    };

    issue_tile(0, kv0);
    if (nkv > 1) issue_tile(1, kv0 + 1);

    // Q fragments (held in regs whole kernel)
    unsigned aq[8][4];
    {
        const float* qp = &g_Q[(size_t)(qrow0 + r0l) * DHEAD];
        #pragma unroll
        for (int k8 = 0; k8 < 8; k8++) {
            int c = k8 * 8 + qd;
            aq[k8][0] = f2tf(qp[c]);
            aq[k8][1] = f2tf(qp[8 * DHEAD + c]);
            aq[k8][2] = f2tf(qp[c + 4]);
            aq[k8][3] = f2tf(qp[8 * DHEAD + c + 4]);
        }
    }

    if (nkv > 1) cpwait<1>(); else cpwait<0>();
    __syncthreads();

    float o[8][4] = {};
    float mr0 = -1e30f, mr1 = -1e30f, lr0 = 0.f, lr1 = 0.f;
    const float scale = 0.03125f;  // 1/sqrt(d_model=1024)

    #pragma unroll 1
    for (int kt = 0; kt < nkv; kt++) {
        const int cur = kt & 1;
        const int ktg = kv0 + kt;

        // ---- S = Q @ K^T  (warp owns 16 rows x 64 cols) ----
        float s[8][4] = {};
        #pragma unroll
        for (int k8 = 0; k8 < 8; k8++) {
            int c = k8 * 8 + qd;
            #pragma unroll
            for (int nt = 0; nt < 8; nt++) {
                int n = nt * 8 + gid;
                unsigned b0 = fbits(Ks[cur][n][c]);
                unsigned b1 = fbits(Ks[cur][n][c + 4]);
                mma_tf32(s[nt], aq[k8][0], aq[k8][1], aq[k8][2], aq[k8][3], b0, b1);
            }
        }
        #pragma unroll
        for (int nt = 0; nt < 8; nt++)
            #pragma unroll
            for (int j = 0; j < 4; j++)
                s[nt][j] *= scale;

        if (ktg == qt) {   // diagonal tile: causal mask
            const int ra = qt * 64 + r0l, rb = ra + 8;
            #pragma unroll
            for (int nt = 0; nt < 8; nt++) {
                int cb = ktg * 64 + nt * 8 + 2 * qd;
                if (cb     > ra) s[nt][0] = -1e30f;
                if (cb + 1 > ra) s[nt][1] = -1e30f;
                if (cb     > rb) s[nt][2] = -1e30f;
                if (cb + 1 > rb) s[nt][3] = -1e30f;
            }
        }

        // ---- warp-local softmax (rows r0l, r0l+8) ----
        float tm0 = -1e30f, tm1 = -1e30f;
        #pragma unroll
        for (int nt = 0; nt < 8; nt++) {
            tm0 = fmaxf(tm0, fmaxf(s[nt][0], s[nt][1]));
            tm1 = fmaxf(tm1, fmaxf(s[nt][2], s[nt][3]));
        }
        tm0 = fmaxf(tm0, __shfl_xor_sync(0xffffffffu, tm0, 1));
        tm0 = fmaxf(tm0, __shfl_xor_sync(0xffffffffu, tm0, 2));
        tm1 = fmaxf(tm1, __shfl_xor_sync(0xffffffffu, tm1, 1));
        tm1 = fmaxf(tm1, __shfl_xor_sync(0xffffffffu, tm1, 2));

        float mn0 = fmaxf(mr0, tm0), mn1 = fmaxf(mr1, tm1);
        float corr0 = __expf(mr0 - mn0), corr1 = __expf(mr1 - mn1);
        mr0 = mn0; mr1 = mn1;

        float ps0 = 0.f, ps1 = 0.f;
        #pragma unroll
        for (int nt = 0; nt < 8; nt++) {
            float p0 = __expf(s[nt][0] - mn0);
            float p1 = __expf(s[nt][1] - mn0);
            float p2 = __expf(s[nt][2] - mn1);
            float p3 = __expf(s[nt][3] - mn1);
            ps0 += p0 + p1;
            ps1 += p2 + p3;
            int cb = nt * 8 + 2 * qd;
            *(float2*)&Ps[r0l][cb] =
                make_float2(__uint_as_float(f2tf(p0)), __uint_as_float(f2tf(p1)));
            *(float2*)&Ps[r0l + 8][cb] =
                make_float2(__uint_as_float(f2tf(p2)), __uint_as_float(f2tf(p3)));
        }
        ps0 += __shfl_xor_sync(0xffffffffu, ps0, 1);
        ps0 += __shfl_xor_sync(0xffffffffu, ps0, 2);
        ps1 += __shfl_xor_sync(0xffffffffu, ps1, 1);
        ps1 += __shfl_xor_sync(0xffffffffu, ps1, 2);
        lr0 = lr0 * corr0 + ps0;
        lr1 = lr1 * corr1 + ps1;

        #pragma unroll
        for (int nt = 0; nt < 8; nt++) {
            o[nt][0] *= corr0; o[nt][1] *= corr0;
            o[nt][2] *= corr1; o[nt][3] *= corr1;
        }

        __syncwarp();   // Ps rows are warp-private: warp-level visibility suffices

        // ---- O += P @ V   (V == K tile) ----
        #pragma unroll
        for (int k8 = 0; k8 < 8; k8++) {
            int c = k8 * 8 + qd;
            unsigned a0 = fbits(Ps[r0l][c]);
            unsigned a1 = fbits(Ps[r0l + 8][c]);
            unsigned a2 = fbits(Ps[r0l][c + 4]);
            unsigned a3 = fbits(Ps[r0l + 8][c + 4]);
            #pragma unroll
            for (int nt = 0; nt < 8; nt++) {
                int d = nt * 8 + gid;
                unsigned b0 = fbits(Ks[cur][c][d]);
                unsigned b1 = fbits(Ks[cur][c + 4][d]);
                mma_tf32(o[nt], a0, a1, a2, a3, b0, b1);
            }
        }

        // ---- pipeline: refill cur with tile kt+2, ensure kt+1 ready ----
        if (kt + 1 < nkv) {
            __syncthreads();   // all warps done reading Ks[cur]
            if (kt + 2 < nkv) { issue_tile(cur, kv0 + kt + 2); cpwait<1>(); }
            else              { cpwait<0>(); }
            __syncthreads();   // Ks[cur^1] (tile kt+1) visible to all
        }
    }

    // ---- epilogue ----
    if (nch == 1) {
        float inv0 = 1.0f / lr0, inv1 = 1.0f / lr1;
        #pragma unroll
        for (int nt = 0; nt < 8; nt++) {
            int cb = nt * 8 + 2 * qd;
            *(float2*)&out[(size_t)(qrow0 + r0l) * DHEAD + cb] =
                make_float2(o[nt][0] * inv0, o[nt][1] * inv0);
            *(float2*)&out[(size_t)(qrow0 + r0l + 8) * DHEAD + cb] =
                make_float2(o[nt][2] * inv1, o[nt][3] * inv1);
        }
    } else {
        const int pid = (b * 32 + qt) * 4 + ck;
        float* pp = &g_part[(size_t)pid * 4096];
        #pragma unroll
        for (int nt = 0; nt < 8; nt++) {
            int cb = nt * 8 + 2 * qd;
            *(float2*)&pp[(size_t)r0l * 64 + cb]       = make_float2(o[nt][0], o[nt][1]);
            *(float2*)&pp[(size_t)(r0l + 8) * 64 + cb] = make_float2(o[nt][2], o[nt][3]);
        }
        if (qd == 0) {
            g_pm[pid * 64 + r0l]     = mr0;
            g_pm[pid * 64 + r0l + 8] = mr1;
            g_pl[pid * 64 + r0l]     = lr0;
            g_pl[pid * 64 + r0l + 8] = lr1;
        }
    }
}

// ---------------------------------------------------------------------------
// Combine: merge split-KV partials for qt >= 8. grid = (24, BSZ), block 256.
// Thread handles (row = tid>>2, 16 cols at (tid&3)*16).
// ---------------------------------------------------------------------------
__global__ __launch_bounds__(256) void combine(float* __restrict__ out)
{
    const int qt  = 8 + blockIdx.x;
    const int b   = blockIdx.y;
    const int nch = qt / 8 + 1;
    const int tid = threadIdx.x;
    const int row = tid >> 2;
    const int cs  = (tid & 3) * 16;
    const int pb  = (b * 32 + qt) * 4;

    float m = -1e30f;
    for (int i = 0; i < nch; i++)
        m = fmaxf(m, g_pm[(pb + i) * 64 + row]);

    float l = 0.f;
    float acc[16] = {};
    for (int i = 0; i < nch; i++) {
        float wgt = __expf(g_pm[(pb + i) * 64 + row] - m);
        l += wgt * g_pl[(pb + i) * 64 + row];
        const float4* p = (const float4*)&g_part[(size_t)(pb + i) * 4096 + row * 64 + cs];
        #pragma unroll
        for (int j = 0; j < 4; j++) {
            float4 v = p[j];
            acc[4*j + 0] += wgt * v.x;
            acc[4*j + 1] += wgt * v.y;
            acc[4*j + 2] += wgt * v.z;
            acc[4*j + 3] += wgt * v.w;
        }
    }
    float inv = 1.0f / l;
    float4* op = (float4*)&out[(size_t)(b * TLEN + qt * 64 + row) * DHEAD + cs];
    #pragma unroll
    for (int j = 0; j < 4; j++)
        op[j] = make_float4(acc[4*j] * inv, acc[4*j + 1] * inv,
                            acc[4*j + 2] * inv, acc[4*j + 3] * inv);
}

extern "C" void kernel_launch(void* const* d_in, const int* in_sizes, int n_in,
                              void* d_out, int out_size)
{
    const float* x  = (const float*)d_in[0];
    const float* Wq = (const float*)d_in[1];
    const float* Wk = (const float*)d_in[2];
    // d_in[3] (W_V) intentionally unused: reference computes V with W_K.
    float* out = (float*)d_out;

    proj_mma<<<dim3(128, 2), 256>>>(x, Wq, Wk);
    attn_mma<<<dim3(80, BSZ), 128>>>(out);
    combine <<<dim3(24, BSZ), 256>>>(out);
}

// round 6
// speedup vs baseline: 2.8629x; 1.0793x over previous
#include <cuda_runtime.h>
#include <cstdint>

#define BSZ    4
#define TLEN   2048
#define DMODEL 1024
#define DHEAD  64
#define NROWS  (BSZ*TLEN)

// Scratch (allocation-free rule: __device__ globals)
__device__ float g_Q[NROWS*DHEAD];
__device__ float g_K[NROWS*DHEAD];
// split-KV partials: [b][qt(32)][chunk(4)][64 rows][64 cols], plus per-row m,l
__device__ float g_part[4*32*4*64*64];
__device__ float g_pm[4*32*4*64];
__device__ float g_pl[4*32*4*64];

// ---------------------------------------------------------------------------
// helpers
// ---------------------------------------------------------------------------
__device__ __forceinline__ unsigned f2tf(float a) {
    unsigned r;
    asm("cvt.rna.tf32.f32 %0, %1;" : "=r"(r) : "f"(a));
    return r;
}
__device__ __forceinline__ unsigned fbits(float f) { return __float_as_uint(f); }

__device__ __forceinline__ void mma_tf32(float c[4],
                                         unsigned a0, unsigned a1, unsigned a2, unsigned a3,
                                         unsigned b0, unsigned b1) {
    asm volatile(
        "mma.sync.aligned.m16n8k8.row.col.f32.tf32.tf32.f32 "
        "{%0,%1,%2,%3}, {%4,%5,%6,%7}, {%8,%9}, {%0,%1,%2,%3};"
        : "+f"(c[0]), "+f"(c[1]), "+f"(c[2]), "+f"(c[3])
        : "r"(a0), "r"(a1), "r"(a2), "r"(a3), "r"(b0), "r"(b1));
}

__device__ __forceinline__ void cp16(uint32_t dst, const void* src) {
    asm volatile("cp.async.cg.shared.global [%0], [%1], 16;" :: "r"(dst), "l"(src));
}
__device__ __forceinline__ void cpcommit() {
    asm volatile("cp.async.commit_group;");
}
template<int N> __device__ __forceinline__ void cpwait() {
    asm volatile("cp.async.wait_group %0;" :: "n"(N));
}

// ---------------------------------------------------------------------------
// Projection (single tf32): out[row][d] = sum_c x[row][c] * W[d][c]
// grid = (128, 2): y==0 -> W_Q -> g_Q ; y==1 -> W_K -> g_K.  BM=64, BN=64, BK=32.
// block 256 = 8 warps: 4 m-warps (16 rows) x 2 n-warps (32 cols).
// Fragment-packed smem: A-frag = 1 LDS.128, B-frag = 1 LDS.64.
// ---------------------------------------------------------------------------
__global__ __launch_bounds__(256, 3) void proj_mma(
    const float* __restrict__ x,
    const float* __restrict__ Wq,
    const float* __restrict__ Wk)
{
    // XsP[pair][k8*4+qd] = {X[r][c], X[r+8][c], X[r][c+4], X[r+8][c+4]}
    //   pair p: r = (p>>3)*16 + (p&7);  c = k8*8+qd.  17 = 16 slots + 1 pad.
    __shared__ float4 XsP[32][17];
    // BsP[k8][n][qd] = {W[n][c], W[n][c+4]}
    __shared__ float2 BsP[4][64][4];

    const float* W    = blockIdx.y ? Wk : Wq;
    float*       outp = blockIdx.y ? g_K : g_Q;

    const int tid  = threadIdx.x;
    const int lane = tid & 31;
    const int w    = tid >> 5;
    const int gid  = lane >> 2;
    const int qd   = lane & 3;
    const int mw   = w & 3;
    const int nw   = w >> 2;
    const int row0 = blockIdx.x * 64;

    // loader coords: 2 float4 per tile per thread (64 rows x 32 cols = 512 f4)
    const int lr[2]   = { tid >> 3, (tid + 256) >> 3 };
    const int lsg     = (tid & 7) * 4;          // col start within BK chunk
    const int lk8     = lsg >> 3;
    const int lhalf   = (lsg >> 2) & 1;
    const int lp[2]   = { ((lr[0] >> 4) << 3) | (lr[0] & 7),
                          ((lr[1] >> 4) << 3) | (lr[1] & 7) };
    const int lhi[2]  = { (lr[0] >> 3) & 1, (lr[1] >> 3) & 1 };

    float acc[4][4] = {};

    float4 px[2], pw[2];
    #pragma unroll
    for (int i = 0; i < 2; i++) {
        px[i] = *(const float4*)&x[(size_t)(row0 + lr[i]) * DMODEL + lsg];
        pw[i] = *(const float4*)&W[(size_t)lr[i] * DMODEL + lsg];
    }

    for (int kc = 0; kc < DMODEL; kc += 32) {
        __syncthreads();   // WAR: previous MMA phase done with XsP/BsP

        // store prefetched tiles, tf32-rounded, fragment-packed
        #pragma unroll
        for (int i = 0; i < 2; i++) {
            float vx[4] = {px[i].x, px[i].y, px[i].z, px[i].w};
            float vw[4] = {pw[i].x, pw[i].y, pw[i].z, pw[i].w};
            int slotA = lhalf * 2 + lhi[i];
            #pragma unroll
            for (int j = 0; j < 4; j++) {
                ((float*)&XsP[lp[i]][lk8 * 4 + j])[slotA] =
                    __uint_as_float(f2tf(vx[j]));
                ((float*)&BsP[lk8][lr[i]][j])[lhalf] =
                    __uint_as_float(f2tf(vw[j]));
            }
        }

        // prefetch next chunk (wrap on last iter; harmless, keeps code uniform)
        int kn = (kc + 32 < DMODEL) ? kc + 32 : 0;
        #pragma unroll
        for (int i = 0; i < 2; i++) {
            px[i] = *(const float4*)&x[(size_t)(row0 + lr[i]) * DMODEL + kn + lsg];
            pw[i] = *(const float4*)&W[(size_t)lr[i] * DMODEL + kn + lsg];
        }
        __syncthreads();   // tiles visible

        #pragma unroll
        for (int k8 = 0; k8 < 4; k8++) {
            float4 af = XsP[mw * 8 + gid][k8 * 4 + qd];      // 1 x LDS.128
            unsigned a0 = fbits(af.x), a1 = fbits(af.y);
            unsigned a2 = fbits(af.z), a3 = fbits(af.w);
            #pragma unroll
            for (int nt = 0; nt < 4; nt++) {
                int n = nw * 32 + nt * 8 + gid;
                float2 bf = BsP[k8][n][qd];                  // 1 x LDS.64
                mma_tf32(acc[nt], a0, a1, a2, a3, fbits(bf.x), fbits(bf.y));
            }
        }
    }

    const int r = row0 + mw * 16 + gid;
    #pragma unroll
    for (int nt = 0; nt < 4; nt++) {
        int cb = nw * 32 + nt * 8 + 2 * qd;
        *(float2*)&outp[(size_t)r * DHEAD + cb] =
            make_float2(acc[nt][0], acc[nt][1]);
        *(float2*)&outp[(size_t)(r + 8) * DHEAD + cb] =
            make_float2(acc[nt][2], acc[nt][3]);
    }
}

// ---------------------------------------------------------------------------
// Flash attention, split-KV. BM=64, BN=64. 4 warps, each owns 16 full rows ->
// softmax is entirely warp-local (no cross-warp smem, no softmax barriers).
// grid = (80 chunks, BSZ). Chunk decode: qt band t = qt/8 has t+1 chunks.
// V == K (reference bug). Partials (O,m,l) to scratch when nch > 1.
// ---------------------------------------------------------------------------
__global__ __launch_bounds__(128, 3) void attn_mma(float* __restrict__ out)
{
    __shared__ float Ks[2][64][68];
    __shared__ float Ps[64][68];

    const int b   = blockIdx.y;
    const int cid = blockIdx.x;

    // decode (qt, ck): band starts 0,8,24,48
    const int t     = (cid >= 48) ? 3 : (cid >= 24) ? 2 : (cid >= 8) ? 1 : 0;
    const int strt  = (t == 3) ? 48 : (t == 2) ? 24 : (t == 1) ? 8 : 0;
    const int rem   = cid - strt;
    const int qt    = 8 * t + rem / (t + 1);
    const int ck    = rem % (t + 1);
    const int ntile = qt + 1;
    const int nch   = t + 1;
    const int bse   = ntile / nch;
    const int ext   = ntile % nch;
    const int nkv   = bse + (ck < ext ? 1 : 0);
    const int kv0   = ck * bse + (ck < ext ? ck : ext);

    const int tid  = threadIdx.x;
    const int lane = tid & 31;
    const int w    = tid >> 5;
    const int gid  = lane >> 2;
    const int qd   = lane & 3;
    const int r0l  = w * 16 + gid;

    const int qrow0 = b * TLEN + qt * 64;
    const uint32_t ks_u32 = (uint32_t)__cvta_generic_to_shared(&Ks[0][0][0]);

    // --- cp.async K-tile issue (16B x 8 per thread = 16KB tile) ---
    auto issue_tile = [&](int buf, int ktg) {
        const float* kb = &g_K[(size_t)(b * TLEN + ktg * 64) * DHEAD];
        #pragma unroll
        for (int i = 0; i < 8; i++) {
            int lin = i * 128 + tid;
            int row = lin >> 4, sg = (lin & 15) * 4;
            cp16(ks_u32 + (uint32_t)(((buf * 64 + row) * 68 + sg) * 4),
                 kb + row * 64 + sg);
        }
        cpcommit();
    };

    issue_tile(0, kv0);
    if (nkv > 1) issue_tile(1, kv0 + 1);

    // Q fragments (held in regs whole kernel)
    unsigned aq[8][4];
    {
        const float* qp = &g_Q[(size_t)(qrow0 + r0l) * DHEAD];
        #pragma unroll
        for (int k8 = 0; k8 < 8; k8++) {
            int c = k8 * 8 + qd;
            aq[k8][0] = f2tf(qp[c]);
            aq[k8][1] = f2tf(qp[8 * DHEAD + c]);
            aq[k8][2] = f2tf(qp[c + 4]);
            aq[k8][3] = f2tf(qp[8 * DHEAD + c + 4]);
        }
    }

    if (nkv > 1) cpwait<1>(); else cpwait<0>();
    __syncthreads();

    float o[8][4] = {};
    float mr0 = -1e30f, mr1 = -1e30f, lr0 = 0.f, lr1 = 0.f;
    const float scale = 0.03125f;  // 1/sqrt(d_model=1024)

    #pragma unroll 1
    for (int kt = 0; kt < nkv; kt++) {
        const int cur = kt & 1;
        const int ktg = kv0 + kt;

        // ---- S = Q @ K^T  (warp owns 16 rows x 64 cols) ----
        float s[8][4] = {};
        #pragma unroll
        for (int k8 = 0; k8 < 8; k8++) {
            int c = k8 * 8 + qd;
            #pragma unroll
            for (int nt = 0; nt < 8; nt++) {
                int n = nt * 8 + gid;
                unsigned b0 = fbits(Ks[cur][n][c]);
                unsigned b1 = fbits(Ks[cur][n][c + 4]);
                mma_tf32(s[nt], aq[k8][0], aq[k8][1], aq[k8][2], aq[k8][3], b0, b1);
            }
        }
        #pragma unroll
        for (int nt = 0; nt < 8; nt++)
            #pragma unroll
            for (int j = 0; j < 4; j++)
                s[nt][j] *= scale;

        if (ktg == qt) {   // diagonal tile: causal mask
            const int ra = qt * 64 + r0l, rb = ra + 8;
            #pragma unroll
            for (int nt = 0; nt < 8; nt++) {
                int cb = ktg * 64 + nt * 8 + 2 * qd;
                if (cb     > ra) s[nt][0] = -1e30f;
                if (cb + 1 > ra) s[nt][1] = -1e30f;
                if (cb     > rb) s[nt][2] = -1e30f;
                if (cb + 1 > rb) s[nt][3] = -1e30f;
            }
        }

        // ---- warp-local softmax (rows r0l, r0l+8) ----
        float tm0 = -1e30f, tm1 = -1e30f;
        #pragma unroll
        for (int nt = 0; nt < 8; nt++) {
            tm0 = fmaxf(tm0, fmaxf(s[nt][0], s[nt][1]));
            tm1 = fmaxf(tm1, fmaxf(s[nt][2], s[nt][3]));
        }
        tm0 = fmaxf(tm0, __shfl_xor_sync(0xffffffffu, tm0, 1));
        tm0 = fmaxf(tm0, __shfl_xor_sync(0xffffffffu, tm0, 2));
        tm1 = fmaxf(tm1, __shfl_xor_sync(0xffffffffu, tm1, 1));
        tm1 = fmaxf(tm1, __shfl_xor_sync(0xffffffffu, tm1, 2));

        float mn0 = fmaxf(mr0, tm0), mn1 = fmaxf(mr1, tm1);
        float corr0 = __expf(mr0 - mn0), corr1 = __expf(mr1 - mn1);
        mr0 = mn0; mr1 = mn1;

        float ps0 = 0.f, ps1 = 0.f;
        #pragma unroll
        for (int nt = 0; nt < 8; nt++) {
            float p0 = __expf(s[nt][0] - mn0);
            float p1 = __expf(s[nt][1] - mn0);
            float p2 = __expf(s[nt][2] - mn1);
            float p3 = __expf(s[nt][3] - mn1);
            ps0 += p0 + p1;
            ps1 += p2 + p3;
            int cb = nt * 8 + 2 * qd;
            *(float2*)&Ps[r0l][cb] =
                make_float2(__uint_as_float(f2tf(p0)), __uint_as_float(f2tf(p1)));
            *(float2*)&Ps[r0l + 8][cb] =
                make_float2(__uint_as_float(f2tf(p2)), __uint_as_float(f2tf(p3)));
        }
        ps0 += __shfl_xor_sync(0xffffffffu, ps0, 1);
        ps0 += __shfl_xor_sync(0xffffffffu, ps0, 2);
        ps1 += __shfl_xor_sync(0xffffffffu, ps1, 1);
        ps1 += __shfl_xor_sync(0xffffffffu, ps1, 2);
        lr0 = lr0 * corr0 + ps0;
        lr1 = lr1 * corr1 + ps1;

        #pragma unroll
        for (int nt = 0; nt < 8; nt++) {
            o[nt][0] *= corr0; o[nt][1] *= corr0;
            o[nt][2] *= corr1; o[nt][3] *= corr1;
        }

        __syncwarp();   // Ps rows are warp-private: warp-level visibility suffices

        // ---- O += P @ V   (V == K tile) ----
        #pragma unroll
        for (int k8 = 0; k8 < 8; k8++) {
            int c = k8 * 8 + qd;
            unsigned a0 = fbits(Ps[r0l][c]);
            unsigned a1 = fbits(Ps[r0l + 8][c]);
            unsigned a2 = fbits(Ps[r0l][c + 4]);
            unsigned a3 = fbits(Ps[r0l + 8][c + 4]);
            #pragma unroll
            for (int nt = 0; nt < 8; nt++) {
                int d = nt * 8 + gid;
                unsigned b0 = fbits(Ks[cur][c][d]);
                unsigned b1 = fbits(Ks[cur][c + 4][d]);
                mma_tf32(o[nt], a0, a1, a2, a3, b0, b1);
            }
        }

        // ---- pipeline: refill cur with tile kt+2, ensure kt+1 ready ----
        if (kt + 1 < nkv) {
            __syncthreads();   // all warps done reading Ks[cur]
            if (kt + 2 < nkv) { issue_tile(cur, kv0 + kt + 2); cpwait<1>(); }
            else              { cpwait<0>(); }
            __syncthreads();   // Ks[cur^1] (tile kt+1) visible to all
        }
    }

    // ---- epilogue ----
    if (nch == 1) {
        float inv0 = 1.0f / lr0, inv1 = 1.0f / lr1;
        #pragma unroll
        for (int nt = 0; nt < 8; nt++) {
            int cb = nt * 8 + 2 * qd;
            *(float2*)&out[(size_t)(qrow0 + r0l) * DHEAD + cb] =
                make_float2(o[nt][0] * inv0, o[nt][1] * inv0);
            *(float2*)&out[(size_t)(qrow0 + r0l + 8) * DHEAD + cb] =
                make_float2(o[nt][2] * inv1, o[nt][3] * inv1);
        }
    } else {
        const int pid = (b * 32 + qt) * 4 + ck;
        float* pp = &g_part[(size_t)pid * 4096];
        #pragma unroll
        for (int nt = 0; nt < 8; nt++) {
            int cb = nt * 8 + 2 * qd;
            *(float2*)&pp[(size_t)r0l * 64 + cb]       = make_float2(o[nt][0], o[nt][1]);
            *(float2*)&pp[(size_t)(r0l + 8) * 64 + cb] = make_float2(o[nt][2], o[nt][3]);
        }
        if (qd == 0) {
            g_pm[pid * 64 + r0l]     = mr0;
            g_pm[pid * 64 + r0l + 8] = mr1;
            g_pl[pid * 64 + r0l]     = lr0;
            g_pl[pid * 64 + r0l + 8] = lr1;
        }
    }
}

// ---------------------------------------------------------------------------
// Combine: merge split-KV partials for qt >= 8. grid = (24, BSZ), block 256.
// Thread handles (row = tid>>2, 16 cols at (tid&3)*16).
// ---------------------------------------------------------------------------
__global__ __launch_bounds__(256) void combine(float* __restrict__ out)
{
    const int qt  = 8 + blockIdx.x;
    const int b   = blockIdx.y;
    const int nch = qt / 8 + 1;
    const int tid = threadIdx.x;
    const int row = tid >> 2;
    const int cs  = (tid & 3) * 16;
    const int pb  = (b * 32 + qt) * 4;

    float m = -1e30f;
    for (int i = 0; i < nch; i++)
        m = fmaxf(m, g_pm[(pb + i) * 64 + row]);

    float l = 0.f;
    float acc[16] = {};
    for (int i = 0; i < nch; i++) {
        float wgt = __expf(g_pm[(pb + i) * 64 + row] - m);
        l += wgt * g_pl[(pb + i) * 64 + row];
        const float4* p = (const float4*)&g_part[(size_t)(pb + i) * 4096 + row * 64 + cs];
        #pragma unroll
        for (int j = 0; j < 4; j++) {
            float4 v = p[j];
            acc[4*j + 0] += wgt * v.x;
            acc[4*j + 1] += wgt * v.y;
            acc[4*j + 2] += wgt * v.z;
            acc[4*j + 3] += wgt * v.w;
        }
    }
    float inv = 1.0f / l;
    float4* op = (float4*)&out[(size_t)(b * TLEN + qt * 64 + row) * DHEAD + cs];
    #pragma unroll
    for (int j = 0; j < 4; j++)
        op[j] = make_float4(acc[4*j] * inv, acc[4*j + 1] * inv,
                            acc[4*j + 2] * inv, acc[4*j + 3] * inv);
}

extern "C" void kernel_launch(void* const* d_in, const int* in_sizes, int n_in,
                              void* d_out, int out_size)
{
    const float* x  = (const float*)d_in[0];
    const float* Wq = (const float*)d_in[1];
    const float* Wk = (const float*)d_in[2];
    // d_in[3] (W_V) intentionally unused: reference computes V with W_K.
    float* out = (float*)d_out;

    proj_mma<<<dim3(128, 2), 256>>>(x, Wq, Wk);
    attn_mma<<<dim3(80, BSZ), 128>>>(out);
    combine <<<dim3(24, BSZ), 256>>>(out);
}

// round 7
// speedup vs baseline: 3.3511x; 1.1705x over previous
#include <cuda_runtime.h>
#include <cstdint>

#define BSZ    4
#define TLEN   2048
#define DMODEL 1024
#define DHEAD  64
#define NROWS  (BSZ*TLEN)

// Scratch (allocation-free rule: __device__ globals)
__device__ float g_Q[NROWS*DHEAD];
__device__ float g_K[NROWS*DHEAD];
// W fragment-pack: [sel(2)][k8g(128)][n(64)][qd(4)] -> {W[n][c], W[n][c+4]}, c=k8g*8+qd
__device__ float2 g_Wp[2*128*64*4];
// split-KV partials: [b][qt(32)][chunk(4)][64 rows][64 cols], plus per-row m,l
__device__ float g_part[4*32*4*64*64];
__device__ float g_pm[4*32*4*64];
__device__ float g_pl[4*32*4*64];

// ---------------------------------------------------------------------------
// helpers
// ---------------------------------------------------------------------------
__device__ __forceinline__ unsigned f2tf(float a) {
    unsigned r;
    asm("cvt.rna.tf32.f32 %0, %1;" : "=r"(r) : "f"(a));
    return r;
}
__device__ __forceinline__ unsigned fbits(float f) { return __float_as_uint(f); }

__device__ __forceinline__ void mma_tf32(float c[4],
                                         unsigned a0, unsigned a1, unsigned a2, unsigned a3,
                                         unsigned b0, unsigned b1) {
    asm volatile(
        "mma.sync.aligned.m16n8k8.row.col.f32.tf32.tf32.f32 "
        "{%0,%1,%2,%3}, {%4,%5,%6,%7}, {%8,%9}, {%0,%1,%2,%3};"
        : "+f"(c[0]), "+f"(c[1]), "+f"(c[2]), "+f"(c[3])
        : "r"(a0), "r"(a1), "r"(a2), "r"(a3), "r"(b0), "r"(b1));
}

__device__ __forceinline__ void cp16(uint32_t dst, const void* src) {
    asm volatile("cp.async.cg.shared.global [%0], [%1], 16;" :: "r"(dst), "l"(src));
}
__device__ __forceinline__ void cpcommit() {
    asm volatile("cp.async.commit_group;");
}
template<int N> __device__ __forceinline__ void cpwait() {
    asm volatile("cp.async.wait_group %0;" :: "n"(N));
}

// ---------------------------------------------------------------------------
// Prep: pack W_Q, W_K into tf32-rounded fragment layout (one float2 per thread x2).
// grid = 128, block = 256  (65536 float2 total)
// ---------------------------------------------------------------------------
__global__ __launch_bounds__(256) void prep_w(
    const float* __restrict__ Wq, const float* __restrict__ Wk)
{
    #pragma unroll
    for (int h = 0; h < 2; h++) {
        int idx  = h * 32768 + blockIdx.x * 256 + threadIdx.x;
        int sel  = idx >> 15;
        int rem  = idx & 32767;
        int k8g  = rem >> 8;
        int n    = (rem >> 2) & 63;
        int qd   = rem & 3;
        int c    = k8g * 8 + qd;
        const float* src = sel ? Wk : Wq;
        float w0 = src[(size_t)n * DMODEL + c];
        float w1 = src[(size_t)n * DMODEL + c + 4];
        g_Wp[idx] = make_float2(__uint_as_float(f2tf(w0)),
                                __uint_as_float(f2tf(w1)));
    }
}

// ---------------------------------------------------------------------------
// Projection (single tf32): out[row][d] = sum_c x[row][c] * W[d][c]
// grid = (128, 2): y==0 -> g_Q ; y==1 -> g_K.  BM=64, BN=64, BK=32.
// 8 warps: 4 m-warps x 2 n-warps. A-frag: 1 LDS.128 from packed smem.
// B-frag: 1 coalesced LDG.64 from g_Wp (no W smem at all).
// ---------------------------------------------------------------------------
__global__ __launch_bounds__(256, 3) void proj_mma(const float* __restrict__ x)
{
    // XsP[pair][k8*4+qd] = {X[r][c], X[r+8][c], X[r][c+4], X[r+8][c+4]}
    __shared__ float4 XsP[32][17];

    const int sel  = blockIdx.y;
    float*    outp = sel ? g_K : g_Q;

    const int tid  = threadIdx.x;
    const int lane = tid & 31;
    const int w    = tid >> 5;
    const int gid  = lane >> 2;
    const int qd   = lane & 3;
    const int mw   = w & 3;
    const int nw   = w >> 2;
    const int row0 = blockIdx.x * 64;

    // x loader coords: 2 float4 per chunk per thread
    const int lr[2]  = { tid >> 3, (tid + 256) >> 3 };
    const int lsg    = (tid & 7) * 4;
    const int lk8    = lsg >> 3;
    const int lhalf  = (lsg >> 2) & 1;
    const int lp[2]  = { ((lr[0] >> 4) << 3) | (lr[0] & 7),
                         ((lr[1] >> 4) << 3) | (lr[1] & 7) };
    const int lhi[2] = { (lr[0] >> 3) & 1, (lr[1] >> 3) & 1 };

    // per-warp B pointer base: frag (k8g, nt) at [((sel*128+k8g)*64 + nw*32+nt*8+gid)*4 + qd]
    const float2* wp = &g_Wp[((size_t)sel * 128 * 64 + nw * 32 + gid) * 4 + qd];

    float acc[4][4] = {};

    float4 px[2];
    #pragma unroll
    for (int i = 0; i < 2; i++)
        px[i] = *(const float4*)&x[(size_t)(row0 + lr[i]) * DMODEL + lsg];

    for (int kc = 0; kc < DMODEL; kc += 32) {
        const int k8g0 = kc >> 3;

        // issue all 16 B-frag LDG.64 for this chunk (independent of smem phases)
        float2 bf[4][4];
        #pragma unroll
        for (int k8 = 0; k8 < 4; k8++)
            #pragma unroll
            for (int nt = 0; nt < 4; nt++)
                bf[k8][nt] = wp[((size_t)(k8g0 + k8) * 64 + nt * 8) * 4];

        __syncthreads();   // WAR: previous MMA phase done with XsP

        // store x tile, tf32-rounded, fragment-packed
        #pragma unroll
        for (int i = 0; i < 2; i++) {
            float vx[4] = {px[i].x, px[i].y, px[i].z, px[i].w};
            int slotA = lhalf * 2 + lhi[i];
            #pragma unroll
            for (int j = 0; j < 4; j++)
                ((float*)&XsP[lp[i]][lk8 * 4 + j])[slotA] =
                    __uint_as_float(f2tf(vx[j]));
        }

        // prefetch next x chunk (wrap on last iter; harmless)
        int kn = (kc + 32 < DMODEL) ? kc + 32 : 0;
        #pragma unroll
        for (int i = 0; i < 2; i++)
            px[i] = *(const float4*)&x[(size_t)(row0 + lr[i]) * DMODEL + kn + lsg];

        __syncthreads();   // x tile visible

        #pragma unroll
        for (int k8 = 0; k8 < 4; k8++) {
            float4 af = XsP[mw * 8 + gid][k8 * 4 + qd];      // 1 x LDS.128
            unsigned a0 = fbits(af.x), a1 = fbits(af.y);
            unsigned a2 = fbits(af.z), a3 = fbits(af.w);
            #pragma unroll
            for (int nt = 0; nt < 4; nt++)
                mma_tf32(acc[nt], a0, a1, a2, a3,
                         fbits(bf[k8][nt].x), fbits(bf[k8][nt].y));
        }
    }

    const int r = row0 + mw * 16 + gid;
    #pragma unroll
    for (int nt = 0; nt < 4; nt++) {
        int cb = nw * 32 + nt * 8 + 2 * qd;
        *(float2*)&outp[(size_t)r * DHEAD + cb] =
            make_float2(acc[nt][0], acc[nt][1]);
        *(float2*)&outp[(size_t)(r + 8) * DHEAD + cb] =
            make_float2(acc[nt][2], acc[nt][3]);
    }
}

// ---------------------------------------------------------------------------
// Flash attention, split-KV. BM=64, BN=64. 4 warps, each owns 16 full rows ->
// softmax is entirely warp-local (no cross-warp smem, no softmax barriers).
// grid = (80 chunks, BSZ). Chunk decode: qt band t = qt/8 has t+1 chunks.
// V == K (reference bug). Partials (O,m,l) to scratch when nch > 1.
// ---------------------------------------------------------------------------
__global__ __launch_bounds__(128, 3) void attn_mma(float* __restrict__ out)
{
    __shared__ float Ks[2][64][68];
    __shared__ float Ps[64][68];

    const int b   = blockIdx.y;
    const int cid = blockIdx.x;

    // decode (qt, ck): band starts 0,8,24,48
    const int t     = (cid >= 48) ? 3 : (cid >= 24) ? 2 : (cid >= 8) ? 1 : 0;
    const int strt  = (t == 3) ? 48 : (t == 2) ? 24 : (t == 1) ? 8 : 0;
    const int rem   = cid - strt;
    const int qt    = 8 * t + rem / (t + 1);
    const int ck    = rem % (t + 1);
    const int ntile = qt + 1;
    const int nch   = t + 1;
    const int bse   = ntile / nch;
    const int ext   = ntile % nch;
    const int nkv   = bse + (ck < ext ? 1 : 0);
    const int kv0   = ck * bse + (ck < ext ? ck : ext);

    const int tid  = threadIdx.x;
    const int lane = tid & 31;
    const int w    = tid >> 5;
    const int gid  = lane >> 2;
    const int qd   = lane & 3;
    const int r0l  = w * 16 + gid;

    const int qrow0 = b * TLEN + qt * 64;
    const uint32_t ks_u32 = (uint32_t)__cvta_generic_to_shared(&Ks[0][0][0]);

    // --- cp.async K-tile issue (16B x 8 per thread = 16KB tile) ---
    auto issue_tile = [&](int buf, int ktg) {
        const float* kb = &g_K[(size_t)(b * TLEN + ktg * 64) * DHEAD];
        #pragma unroll
        for (int i = 0; i < 8; i++) {
            int lin = i * 128 + tid;
            int row = lin >> 4, sg = (lin & 15) * 4;
            cp16(ks_u32 + (uint32_t)(((buf * 64 + row) * 68 + sg) * 4),
                 kb + row * 64 + sg);
        }
        cpcommit();
    };

    issue_tile(0, kv0);
    if (nkv > 1) issue_tile(1, kv0 + 1);

    // Q fragments (held in regs whole kernel)
    unsigned aq[8][4];
    {
        const float* qp = &g_Q[(size_t)(qrow0 + r0l) * DHEAD];
        #pragma unroll
        for (int k8 = 0; k8 < 8; k8++) {
            int c = k8 * 8 + qd;
            aq[k8][0] = f2tf(qp[c]);
            aq[k8][1] = f2tf(qp[8 * DHEAD + c]);
            aq[k8][2] = f2tf(qp[c + 4]);
            aq[k8][3] = f2tf(qp[8 * DHEAD + c + 4]);
        }
    }

    if (nkv > 1) cpwait<1>(); else cpwait<0>();
    __syncthreads();

    float o[8][4] = {};
    float mr0 = -1e30f, mr1 = -1e30f, lr0 = 0.f, lr1 = 0.f;
    const float scale = 0.03125f;  // 1/sqrt(d_model=1024)

    #pragma unroll 1
    for (int kt = 0; kt < nkv; kt++) {
        const int cur = kt & 1;
        const int ktg = kv0 + kt;

        // ---- S = Q @ K^T  (warp owns 16 rows x 64 cols) ----
        float s[8][4] = {};
        #pragma unroll
        for (int k8 = 0; k8 < 8; k8++) {
            int c = k8 * 8 + qd;
            #pragma unroll
            for (int nt = 0; nt < 8; nt++) {
                int n = nt * 8 + gid;
                unsigned b0 = fbits(Ks[cur][n][c]);
                unsigned b1 = fbits(Ks[cur][n][c + 4]);
                mma_tf32(s[nt], aq[k8][0], aq[k8][1], aq[k8][2], aq[k8][3], b0, b1);
            }
        }
        #pragma unroll
        for (int nt = 0; nt < 8; nt++)
            #pragma unroll
            for (int j = 0; j < 4; j++)
                s[nt][j] *= scale;

        if (ktg == qt) {   // diagonal tile: causal mask
            const int ra = qt * 64 + r0l, rb = ra + 8;
            #pragma unroll
            for (int nt = 0; nt < 8; nt++) {
                int cb = ktg * 64 + nt * 8 + 2 * qd;
                if (cb     > ra) s[nt][0] = -1e30f;
                if (cb + 1 > ra) s[nt][1] = -1e30f;
                if (cb     > rb) s[nt][2] = -1e30f;
                if (cb + 1 > rb) s[nt][3] = -1e30f;
            }
        }

        // ---- warp-local softmax (rows r0l, r0l+8) ----
        float tm0 = -1e30f, tm1 = -1e30f;
        #pragma unroll
        for (int nt = 0; nt < 8; nt++) {
            tm0 = fmaxf(tm0, fmaxf(s[nt][0], s[nt][1]));
            tm1 = fmaxf(tm1, fmaxf(s[nt][2], s[nt][3]));
        }
        tm0 = fmaxf(tm0, __shfl_xor_sync(0xffffffffu, tm0, 1));
        tm0 = fmaxf(tm0, __shfl_xor_sync(0xffffffffu, tm0, 2));
        tm1 = fmaxf(tm1, __shfl_xor_sync(0xffffffffu, tm1, 1));
        tm1 = fmaxf(tm1, __shfl_xor_sync(0xffffffffu, tm1, 2));

        float mn0 = fmaxf(mr0, tm0), mn1 = fmaxf(mr1, tm1);
        float corr0 = __expf(mr0 - mn0), corr1 = __expf(mr1 - mn1);
        mr0 = mn0; mr1 = mn1;

        float ps0 = 0.f, ps1 = 0.f;
        #pragma unroll
        for (int nt = 0; nt < 8; nt++) {
            float p0 = __expf(s[nt][0] - mn0);
            float p1 = __expf(s[nt][1] - mn0);
            float p2 = __expf(s[nt][2] - mn1);
            float p3 = __expf(s[nt][3] - mn1);
            ps0 += p0 + p1;
            ps1 += p2 + p3;
            int cb = nt * 8 + 2 * qd;
            *(float2*)&Ps[r0l][cb] =
                make_float2(__uint_as_float(f2tf(p0)), __uint_as_float(f2tf(p1)));
            *(float2*)&Ps[r0l + 8][cb] =
                make_float2(__uint_as_float(f2tf(p2)), __uint_as_float(f2tf(p3)));
        }
        ps0 += __shfl_xor_sync(0xffffffffu, ps0, 1);
        ps0 += __shfl_xor_sync(0xffffffffu, ps0, 2);
        ps1 += __shfl_xor_sync(0xffffffffu, ps1, 1);
        ps1 += __shfl_xor_sync(0xffffffffu, ps1, 2);
        lr0 = lr0 * corr0 + ps0;
        lr1 = lr1 * corr1 + ps1;

        #pragma unroll
        for (int nt = 0; nt < 8; nt++) {
            o[nt][0] *= corr0; o[nt][1] *= corr0;
            o[nt][2] *= corr1; o[nt][3] *= corr1;
        }

        __syncwarp();   // Ps rows are warp-private: warp-level visibility suffices

        // ---- O += P @ V   (V == K tile) ----
        #pragma unroll
        for (int k8 = 0; k8 < 8; k8++) {
            int c = k8 * 8 + qd;
            unsigned a0 = fbits(Ps[r0l][c]);
            unsigned a1 = fbits(Ps[r0l + 8][c]);
            unsigned a2 = fbits(Ps[r0l][c + 4]);
            unsigned a3 = fbits(Ps[r0l + 8][c + 4]);
            #pragma unroll
            for (int nt = 0; nt < 8; nt++) {
                int d = nt * 8 + gid;
                unsigned b0 = fbits(Ks[cur][c][d]);
                unsigned b1 = fbits(Ks[cur][c + 4][d]);
                mma_tf32(o[nt], a0, a1, a2, a3, b0, b1);
            }
        }

        // ---- pipeline: refill cur with tile kt+2, ensure kt+1 ready ----
        if (kt + 1 < nkv) {
            __syncthreads();   // all warps done reading Ks[cur]
            if (kt + 2 < nkv) { issue_tile(cur, kv0 + kt + 2); cpwait<1>(); }
            else              { cpwait<0>(); }
            __syncthreads();   // Ks[cur^1] (tile kt+1) visible to all
        }
    }

    // ---- epilogue ----
    if (nch == 1) {
        float inv0 = 1.0f / lr0, inv1 = 1.0f / lr1;
        #pragma unroll
        for (int nt = 0; nt < 8; nt++) {
            int cb = nt * 8 + 2 * qd;
            *(float2*)&out[(size_t)(qrow0 + r0l) * DHEAD + cb] =
                make_float2(o[nt][0] * inv0, o[nt][1] * inv0);
            *(float2*)&out[(size_t)(qrow0 + r0l + 8) * DHEAD + cb] =
                make_float2(o[nt][2] * inv1, o[nt][3] * inv1);
        }
    } else {
        const int pid = (b * 32 + qt) * 4 + ck;
        float* pp = &g_part[(size_t)pid * 4096];
        #pragma unroll
        for (int nt = 0; nt < 8; nt++) {
            int cb = nt * 8 + 2 * qd;
            *(float2*)&pp[(size_t)r0l * 64 + cb]       = make_float2(o[nt][0], o[nt][1]);
            *(float2*)&pp[(size_t)(r0l + 8) * 64 + cb] = make_float2(o[nt][2], o[nt][3]);
        }
        if (qd == 0) {
            g_pm[pid * 64 + r0l]     = mr0;
            g_pm[pid * 64 + r0l + 8] = mr1;
            g_pl[pid * 64 + r0l]     = lr0;
            g_pl[pid * 64 + r0l + 8] = lr1;
        }
    }
}

// ---------------------------------------------------------------------------
// Combine: merge split-KV partials for qt >= 8. grid = (24, BSZ), block 256.
// Thread handles (row = tid>>2, 16 cols at (tid&3)*16).
// ---------------------------------------------------------------------------
__global__ __launch_bounds__(256) void combine(float* __restrict__ out)
{
    const int qt  = 8 + blockIdx.x;
    const int b   = blockIdx.y;
    const int nch = qt / 8 + 1;
    const int tid = threadIdx.x;
    const int row = tid >> 2;
    const int cs  = (tid & 3) * 16;
    const int pb  = (b * 32 + qt) * 4;

    float m = -1e30f;
    for (int i = 0; i < nch; i++)
        m = fmaxf(m, g_pm[(pb + i) * 64 + row]);

    float l = 0.f;
    float acc[16] = {};
    for (int i = 0; i < nch; i++) {
        float wgt = __expf(g_pm[(pb + i) * 64 + row] - m);
        l += wgt * g_pl[(pb + i) * 64 + row];
        const float4* p = (const float4*)&g_part[(size_t)(pb + i) * 4096 + row * 64 + cs];
        #pragma unroll
        for (int j = 0; j < 4; j++) {
            float4 v = p[j];
            acc[4*j + 0] += wgt * v.x;
            acc[4*j + 1] += wgt * v.y;
            acc[4*j + 2] += wgt * v.z;
            acc[4*j + 3] += wgt * v.w;
        }
    }
    float inv = 1.0f / l;
    float4* op = (float4*)&out[(size_t)(b * TLEN + qt * 64 + row) * DHEAD + cs];
    #pragma unroll
    for (int j = 0; j < 4; j++)
        op[j] = make_float4(acc[4*j] * inv, acc[4*j + 1] * inv,
                            acc[4*j + 2] * inv, acc[4*j + 3] * inv);
}

extern "C" void kernel_launch(void* const* d_in, const int* in_sizes, int n_in,
                              void* d_out, int out_size)
{
    const float* x  = (const float*)d_in[0];
    const float* Wq = (const float*)d_in[1];
    const float* Wk = (const float*)d_in[2];
    // d_in[3] (W_V) intentionally unused: reference computes V with W_K.
    float* out = (float*)d_out;

    prep_w  <<<128, 256>>>(Wq, Wk);
    proj_mma<<<dim3(128, 2), 256>>>(x);
    attn_mma<<<dim3(80, BSZ), 128>>>(out);
    combine <<<dim3(24, BSZ), 256>>>(out);
}

// round 8
// speedup vs baseline: 3.5258x; 1.0522x over previous
#include <cuda_runtime.h>
#include <cstdint>

#define BSZ    4
#define TLEN   2048
#define DMODEL 1024
#define DHEAD  64
#define NROWS  (BSZ*TLEN)

// Scratch (allocation-free rule: __device__ globals)
__device__ float g_Q[NROWS*DHEAD];
__device__ float g_K[NROWS*DHEAD];
// W fragment-pack: [sel(2)][k8g(128)][n(64)][qd(4)] -> {W[n][c], W[n][c+4]}, c=k8g*8+qd
__device__ float2 g_Wp[2*128*64*4];
// split-KV partials: [b][qt(32)][chunk(4)][64 rows][64 cols], plus per-row m,l
__device__ float g_part[4*32*4*64*64];
__device__ float g_pm[4*32*4*64];
__device__ float g_pl[4*32*4*64];

// ---------------------------------------------------------------------------
// helpers
// ---------------------------------------------------------------------------
__device__ __forceinline__ unsigned f2tf(float a) {
    unsigned r;
    asm("cvt.rna.tf32.f32 %0, %1;" : "=r"(r) : "f"(a));
    return r;
}
__device__ __forceinline__ unsigned fbits(float f) { return __float_as_uint(f); }

__device__ __forceinline__ void mma_tf32(float c[4],
                                         unsigned a0, unsigned a1, unsigned a2, unsigned a3,
                                         unsigned b0, unsigned b1) {
    asm volatile(
        "mma.sync.aligned.m16n8k8.row.col.f32.tf32.tf32.f32 "
        "{%0,%1,%2,%3}, {%4,%5,%6,%7}, {%8,%9}, {%0,%1,%2,%3};"
        : "+f"(c[0]), "+f"(c[1]), "+f"(c[2]), "+f"(c[3])
        : "r"(a0), "r"(a1), "r"(a2), "r"(a3), "r"(b0), "r"(b1));
}

__device__ __forceinline__ void cp16(uint32_t dst, const void* src) {
    asm volatile("cp.async.cg.shared.global [%0], [%1], 16;" :: "r"(dst), "l"(src));
}
__device__ __forceinline__ void cpcommit() {
    asm volatile("cp.async.commit_group;");
}
template<int N> __device__ __forceinline__ void cpwait() {
    asm volatile("cp.async.wait_group %0;" :: "n"(N));
}

// ---------------------------------------------------------------------------
// Prep: pack W_Q, W_K into tf32-rounded fragment layout (one float2 per thread x2).
// grid = 128, block = 256  (65536 float2 total)
// ---------------------------------------------------------------------------
__global__ __launch_bounds__(256) void prep_w(
    const float* __restrict__ Wq, const float* __restrict__ Wk)
{
    #pragma unroll
    for (int h = 0; h < 2; h++) {
        int idx  = h * 32768 + blockIdx.x * 256 + threadIdx.x;
        int sel  = idx >> 15;
        int rem  = idx & 32767;
        int k8g  = rem >> 8;
        int n    = (rem >> 2) & 63;
        int qd   = rem & 3;
        int c    = k8g * 8 + qd;
        const float* src = sel ? Wk : Wq;
        float w0 = src[(size_t)n * DMODEL + c];
        float w1 = src[(size_t)n * DMODEL + c + 4];
        g_Wp[idx] = make_float2(__uint_as_float(f2tf(w0)),
                                __uint_as_float(f2tf(w1)));
    }
}

// ---------------------------------------------------------------------------
// Fused projection (single tf32): [Q|K][row][*] = x[row][:] @ [Wq|Wk]^T
// BM=32, BN=128 (cols 0..63 -> Q, 64..127 -> K). grid = 256 CTAs.
// 8 warps: 2 m-warps (16 rows) x 4 n-warps (32 cols). x datapath runs ONCE.
// A-frag: 1 LDS.128 from packed smem. B-frag: 1 coalesced LDG.64 from g_Wp.
// ---------------------------------------------------------------------------
__global__ __launch_bounds__(256, 3) void proj_mma(const float* __restrict__ x)
{
    // XsP[pair][k8*4+qd] = {X[r][c], X[r+8][c], X[r][c+4], X[r+8][c+4]}
    //   pair p: r = (p&7) + (p>>3)*16
    __shared__ float4 XsP[16][17];

    const int tid  = threadIdx.x;
    const int lane = tid & 31;
    const int w    = tid >> 5;
    const int gid  = lane >> 2;
    const int qd   = lane & 3;
    const int mw   = w & 1;      // 2 m-warps
    const int nw   = w >> 1;     // 4 n-warps
    const int row0 = blockIdx.x * 32;

    // x loader coords: 1 float4 per chunk per thread (32 rows x 32 cols = 256 f4)
    const int lr    = tid >> 3;
    const int lsg   = (tid & 7) * 4;
    const int lk8   = lsg >> 3;
    const int lhalf = (lsg >> 2) & 1;
    const int lp    = (lr & 7) + ((lr >> 4) << 3);
    const int lhi   = (lr >> 3) & 1;
    const int slotA = lhalf * 2 + lhi;

    // B pointer base: sel = nw>>1, local col band = (nw&1)*32
    const int sel = nw >> 1;
    const float2* wp = &g_Wp[((size_t)sel * 128 * 64 + (nw & 1) * 32 + gid) * 4 + qd];

    float acc[4][4] = {};

    float4 px = *(const float4*)&x[(size_t)(row0 + lr) * DMODEL + lsg];

    for (int kc = 0; kc < DMODEL; kc += 32) {
        const int k8g0 = kc >> 3;

        // issue all 16 B-frag LDG.64 for this chunk
        float2 bf[4][4];
        #pragma unroll
        for (int k8 = 0; k8 < 4; k8++)
            #pragma unroll
            for (int nt = 0; nt < 4; nt++)
                bf[k8][nt] = wp[((size_t)(k8g0 + k8) * 64 + nt * 8) * 4];

        __syncthreads();   // WAR: previous MMA phase done with XsP

        // store x tile, tf32-rounded, fragment-packed
        {
            float vx[4] = {px.x, px.y, px.z, px.w};
            #pragma unroll
            for (int j = 0; j < 4; j++)
                ((float*)&XsP[lp][lk8 * 4 + j])[slotA] =
                    __uint_as_float(f2tf(vx[j]));
        }

        // prefetch next x chunk (wrap on last iter; harmless)
        int kn = (kc + 32 < DMODEL) ? kc + 32 : 0;
        px = *(const float4*)&x[(size_t)(row0 + lr) * DMODEL + kn + lsg];

        __syncthreads();   // x tile visible

        #pragma unroll
        for (int k8 = 0; k8 < 4; k8++) {
            float4 af = XsP[mw * 8 + gid][k8 * 4 + qd];      // 1 x LDS.128
            unsigned a0 = fbits(af.x), a1 = fbits(af.y);
            unsigned a2 = fbits(af.z), a3 = fbits(af.w);
            #pragma unroll
            for (int nt = 0; nt < 4; nt++)
                mma_tf32(acc[nt], a0, a1, a2, a3,
                         fbits(bf[k8][nt].x), fbits(bf[k8][nt].y));
        }
    }

    float* outp = (nw < 2) ? g_Q : g_K;
    const int r = row0 + mw * 16 + gid;
    #pragma unroll
    for (int nt = 0; nt < 4; nt++) {
        int cb = (nw & 1) * 32 + nt * 8 + 2 * qd;
        *(float2*)&outp[(size_t)r * DHEAD + cb] =
            make_float2(acc[nt][0], acc[nt][1]);
        *(float2*)&outp[(size_t)(r + 8) * DHEAD + cb] =
            make_float2(acc[nt][2], acc[nt][3]);
    }
}

// ---------------------------------------------------------------------------
// Flash attention, split-KV. BM=64, BN=64. 4 warps, each owns 16 full rows ->
// softmax is entirely warp-local (no cross-warp smem, no softmax barriers).
// grid = (80 chunks, BSZ). Chunk decode: qt band t = qt/8 has t+1 chunks.
// V == K (reference bug). Partials (O,m,l) to scratch when nch > 1.
// ---------------------------------------------------------------------------
__global__ __launch_bounds__(128, 3) void attn_mma(float* __restrict__ out)
{
    __shared__ float Ks[2][64][68];
    __shared__ float Ps[64][68];

    const int b   = blockIdx.y;
    const int cid = blockIdx.x;

    // decode (qt, ck): band starts 0,8,24,48
    const int t     = (cid >= 48) ? 3 : (cid >= 24) ? 2 : (cid >= 8) ? 1 : 0;
    const int strt  = (t == 3) ? 48 : (t == 2) ? 24 : (t == 1) ? 8 : 0;
    const int rem   = cid - strt;
    const int qt    = 8 * t + rem / (t + 1);
    const int ck    = rem % (t + 1);
    const int ntile = qt + 1;
    const int nch   = t + 1;
    const int bse   = ntile / nch;
    const int ext   = ntile % nch;
    const int nkv   = bse + (ck < ext ? 1 : 0);
    const int kv0   = ck * bse + (ck < ext ? ck : ext);

    const int tid  = threadIdx.x;
    const int lane = tid & 31;
    const int w    = tid >> 5;
    const int gid  = lane >> 2;
    const int qd   = lane & 3;
    const int r0l  = w * 16 + gid;

    const int qrow0 = b * TLEN + qt * 64;
    const uint32_t ks_u32 = (uint32_t)__cvta_generic_to_shared(&Ks[0][0][0]);

    // --- cp.async K-tile issue (16B x 8 per thread = 16KB tile) ---
    auto issue_tile = [&](int buf, int ktg) {
        const float* kb = &g_K[(size_t)(b * TLEN + ktg * 64) * DHEAD];
        #pragma unroll
        for (int i = 0; i < 8; i++) {
            int lin = i * 128 + tid;
            int row = lin >> 4, sg = (lin & 15) * 4;
            cp16(ks_u32 + (uint32_t)(((buf * 64 + row) * 68 + sg) * 4),
                 kb + row * 64 + sg);
        }
        cpcommit();
    };

    issue_tile(0, kv0);
    if (nkv > 1) issue_tile(1, kv0 + 1);

    // Q fragments (held in regs whole kernel)
    unsigned aq[8][4];
    {
        const float* qp = &g_Q[(size_t)(qrow0 + r0l) * DHEAD];
        #pragma unroll
        for (int k8 = 0; k8 < 8; k8++) {
            int c = k8 * 8 + qd;
            aq[k8][0] = f2tf(qp[c]);
            aq[k8][1] = f2tf(qp[8 * DHEAD + c]);
            aq[k8][2] = f2tf(qp[c + 4]);
            aq[k8][3] = f2tf(qp[8 * DHEAD + c + 4]);
        }
    }

    if (nkv > 1) cpwait<1>(); else cpwait<0>();
    __syncthreads();

    float o[8][4] = {};
    float mr0 = -1e30f, mr1 = -1e30f, lr0 = 0.f, lr1 = 0.f;
    const float scale = 0.03125f;  // 1/sqrt(d_model=1024)

    #pragma unroll 1
    for (int kt = 0; kt < nkv; kt++) {
        const int cur = kt & 1;
        const int ktg = kv0 + kt;

        // ---- S = Q @ K^T  (warp owns 16 rows x 64 cols) ----
        float s[8][4] = {};
        #pragma unroll
        for (int k8 = 0; k8 < 8; k8++) {
            int c = k8 * 8 + qd;
            #pragma unroll
            for (int nt = 0; nt < 8; nt++) {
                int n = nt * 8 + gid;
                unsigned b0 = fbits(Ks[cur][n][c]);
                unsigned b1 = fbits(Ks[cur][n][c + 4]);
                mma_tf32(s[nt], aq[k8][0], aq[k8][1], aq[k8][2], aq[k8][3], b0, b1);
            }
        }
        #pragma unroll
        for (int nt = 0; nt < 8; nt++)
            #pragma unroll
            for (int j = 0; j < 4; j++)
                s[nt][j] *= scale;

        if (ktg == qt) {   // diagonal tile: causal mask
            const int ra = qt * 64 + r0l, rb = ra + 8;
            #pragma unroll
            for (int nt = 0; nt < 8; nt++) {
                int cb = ktg * 64 + nt * 8 + 2 * qd;
                if (cb     > ra) s[nt][0] = -1e30f;
                if (cb + 1 > ra) s[nt][1] = -1e30f;
                if (cb     > rb) s[nt][2] = -1e30f;
                if (cb + 1 > rb) s[nt][3] = -1e30f;
            }
        }

        // ---- warp-local softmax (rows r0l, r0l+8) ----
        float tm0 = -1e30f, tm1 = -1e30f;
        #pragma unroll
        for (int nt = 0; nt < 8; nt++) {
            tm0 = fmaxf(tm0, fmaxf(s[nt][0], s[nt][1]));
            tm1 = fmaxf(tm1, fmaxf(s[nt][2], s[nt][3]));
        }
        tm0 = fmaxf(tm0, __shfl_xor_sync(0xffffffffu, tm0, 1));
        tm0 = fmaxf(tm0, __shfl_xor_sync(0xffffffffu, tm0, 2));
        tm1 = fmaxf(tm1, __shfl_xor_sync(0xffffffffu, tm1, 1));
        tm1 = fmaxf(tm1, __shfl_xor_sync(0xffffffffu, tm1, 2));

        float mn0 = fmaxf(mr0, tm0), mn1 = fmaxf(mr1, tm1);
        float corr0 = __expf(mr0 - mn0), corr1 = __expf(mr1 - mn1);
        mr0 = mn0; mr1 = mn1;

        float ps0 = 0.f, ps1 = 0.f;
        #pragma unroll
        for (int nt = 0; nt < 8; nt++) {
            float p0 = __expf(s[nt][0] - mn0);
            float p1 = __expf(s[nt][1] - mn0);
            float p2 = __expf(s[nt][2] - mn1);
            float p3 = __expf(s[nt][3] - mn1);
            ps0 += p0 + p1;
            ps1 += p2 + p3;
            int cb = nt * 8 + 2 * qd;
            *(float2*)&Ps[r0l][cb] =
                make_float2(__uint_as_float(f2tf(p0)), __uint_as_float(f2tf(p1)));
            *(float2*)&Ps[r0l + 8][cb] =
                make_float2(__uint_as_float(f2tf(p2)), __uint_as_float(f2tf(p3)));
        }
        ps0 += __shfl_xor_sync(0xffffffffu, ps0, 1);
        ps0 += __shfl_xor_sync(0xffffffffu, ps0, 2);
        ps1 += __shfl_xor_sync(0xffffffffu, ps1, 1);
        ps1 += __shfl_xor_sync(0xffffffffu, ps1, 2);
        lr0 = lr0 * corr0 + ps0;
        lr1 = lr1 * corr1 + ps1;

        #pragma unroll
        for (int nt = 0; nt < 8; nt++) {
            o[nt][0] *= corr0; o[nt][1] *= corr0;
            o[nt][2] *= corr1; o[nt][3] *= corr1;
        }

        __syncwarp();   // Ps rows are warp-private: warp-level visibility suffices

        // ---- O += P @ V   (V == K tile) ----
        #pragma unroll
        for (int k8 = 0; k8 < 8; k8++) {
            int c = k8 * 8 + qd;
            unsigned a0 = fbits(Ps[r0l][c]);
            unsigned a1 = fbits(Ps[r0l + 8][c]);
            unsigned a2 = fbits(Ps[r0l][c + 4]);
            unsigned a3 = fbits(Ps[r0l + 8][c + 4]);
            #pragma unroll
            for (int nt = 0; nt < 8; nt++) {
                int d = nt * 8 + gid;
                unsigned b0 = fbits(Ks[cur][c][d]);
                unsigned b1 = fbits(Ks[cur][c + 4][d]);
                mma_tf32(o[nt], a0, a1, a2, a3, b0, b1);
            }
        }

        // ---- pipeline: refill cur with tile kt+2, ensure kt+1 ready ----
        if (kt + 1 < nkv) {
            __syncthreads();   // all warps done reading Ks[cur]
            if (kt + 2 < nkv) { issue_tile(cur, kv0 + kt + 2); cpwait<1>(); }
            else              { cpwait<0>(); }
            __syncthreads();   // Ks[cur^1] (tile kt+1) visible to all
        }
    }

    // ---- epilogue ----
    if (nch == 1) {
        float inv0 = 1.0f / lr0, inv1 = 1.0f / lr1;
        #pragma unroll
        for (int nt = 0; nt < 8; nt++) {
            int cb = nt * 8 + 2 * qd;
            *(float2*)&out[(size_t)(qrow0 + r0l) * DHEAD + cb] =
                make_float2(o[nt][0] * inv0, o[nt][1] * inv0);
            *(float2*)&out[(size_t)(qrow0 + r0l + 8) * DHEAD + cb] =
                make_float2(o[nt][2] * inv1, o[nt][3] * inv1);
        }
    } else {
        const int pid = (b * 32 + qt) * 4 + ck;
        float* pp = &g_part[(size_t)pid * 4096];
        #pragma unroll
        for (int nt = 0; nt < 8; nt++) {
            int cb = nt * 8 + 2 * qd;
            *(float2*)&pp[(size_t)r0l * 64 + cb]       = make_float2(o[nt][0], o[nt][1]);
            *(float2*)&pp[(size_t)(r0l + 8) * 64 + cb] = make_float2(o[nt][2], o[nt][3]);
        }
        if (qd == 0) {
            g_pm[pid * 64 + r0l]     = mr0;
            g_pm[pid * 64 + r0l + 8] = mr1;
            g_pl[pid * 64 + r0l]     = lr0;
            g_pl[pid * 64 + r0l + 8] = lr1;
        }
    }
}

// ---------------------------------------------------------------------------
// Combine: merge split-KV partials for qt >= 8.
// grid = (24*4, BSZ): blockIdx.x = qt_idx*4 + col-slice. block 256.
// Each thread: one row (tid>>2) x one float4 (16-col slice + (tid&3)*4).
// ---------------------------------------------------------------------------
__global__ __launch_bounds__(256) void combine(float* __restrict__ out)
{
    const int qt  = 8 + (blockIdx.x >> 2);
    const int csl = blockIdx.x & 3;
    const int b   = blockIdx.y;
    const int nch = qt / 8 + 1;
    const int tid = threadIdx.x;
    const int row = tid >> 2;
    const int col = csl * 16 + (tid & 3) * 4;
    const int pb  = (b * 32 + qt) * 4;

    float m = -1e30f;
    #pragma unroll 4
    for (int i = 0; i < nch; i++)
        m = fmaxf(m, g_pm[(pb + i) * 64 + row]);

    float l = 0.f;
    float acc[4] = {};
    #pragma unroll 4
    for (int i = 0; i < nch; i++) {
        float wgt = __expf(g_pm[(pb + i) * 64 + row] - m);
        l += wgt * g_pl[(pb + i) * 64 + row];
        float4 v = *(const float4*)&g_part[(size_t)(pb + i) * 4096 + row * 64 + col];
        acc[0] += wgt * v.x;
        acc[1] += wgt * v.y;
        acc[2] += wgt * v.z;
        acc[3] += wgt * v.w;
    }
    float inv = 1.0f / l;
    *(float4*)&out[(size_t)(b * TLEN + qt * 64 + row) * DHEAD + col] =
        make_float4(acc[0] * inv, acc[1] * inv, acc[2] * inv, acc[3] * inv);
}

extern "C" void kernel_launch(void* const* d_in, const int* in_sizes, int n_in,
                              void* d_out, int out_size)
{
    const float* x  = (const float*)d_in[0];
    const float* Wq = (const float*)d_in[1];
    const float* Wk = (const float*)d_in[2];
    // d_in[3] (W_V) intentionally unused: reference computes V with W_K.
    float* out = (float*)d_out;

    prep_w  <<<128, 256>>>(Wq, Wk);
    proj_mma<<<256, 256>>>(x);
    attn_mma<<<dim3(80, BSZ), 128>>>(out);
    combine <<<dim3(96, BSZ), 256>>>(out);
}

// round 9
// speedup vs baseline: 3.7945x; 1.0762x over previous
#include <cuda_runtime.h>
#include <cstdint>

#define BSZ    4
#define TLEN   2048
#define DMODEL 1024
#define DHEAD  64
#define NROWS  (BSZ*TLEN)

// Scratch (allocation-free rule: __device__ globals)
__device__ float g_Q[NROWS*DHEAD];
__device__ float g_K[NROWS*DHEAD];
// W fragment-pack: [sel(2)][k8g(128)][n(64)][qd(4)] -> {W[n][c], W[n][c+4]}, c=k8g*8+qd
__device__ float2 g_Wp[2*128*64*4];
// split-KV partials: [b][qt(32)][chunk(<=6)][64 rows][64 cols], plus per-row m,l
__device__ float g_part[4*32*6*64*64];
__device__ float g_pm[4*32*6*64];
__device__ float g_pl[4*32*6*64];
__device__ int   g_cnt[4*32];

// ---------------------------------------------------------------------------
// helpers
// ---------------------------------------------------------------------------
__device__ __forceinline__ unsigned f2tf(float a) {
    unsigned r;
    asm("cvt.rna.tf32.f32 %0, %1;" : "=r"(r) : "f"(a));
    return r;
}
__device__ __forceinline__ unsigned fbits(float f) { return __float_as_uint(f); }

__device__ __forceinline__ void mma_tf32(float c[4],
                                         unsigned a0, unsigned a1, unsigned a2, unsigned a3,
                                         unsigned b0, unsigned b1) {
    asm volatile(
        "mma.sync.aligned.m16n8k8.row.col.f32.tf32.tf32.f32 "
        "{%0,%1,%2,%3}, {%4,%5,%6,%7}, {%8,%9}, {%0,%1,%2,%3};"
        : "+f"(c[0]), "+f"(c[1]), "+f"(c[2]), "+f"(c[3])
        : "r"(a0), "r"(a1), "r"(a2), "r"(a3), "r"(b0), "r"(b1));
}

__device__ __forceinline__ void ldsm4(uint32_t& r0, uint32_t& r1,
                                      uint32_t& r2, uint32_t& r3, uint32_t addr) {
    asm volatile("ldmatrix.sync.aligned.m8n8.x4.shared.b16 {%0,%1,%2,%3}, [%4];"
        : "=r"(r0), "=r"(r1), "=r"(r2), "=r"(r3) : "r"(addr));
}

__device__ __forceinline__ void cp16(uint32_t dst, const void* src) {
    asm volatile("cp.async.cg.shared.global [%0], [%1], 16;" :: "r"(dst), "l"(src));
}
__device__ __forceinline__ void cpcommit() {
    asm volatile("cp.async.commit_group;");
}
template<int N> __device__ __forceinline__ void cpwait() {
    asm volatile("cp.async.wait_group %0;" :: "n"(N));
}

// ---------------------------------------------------------------------------
// Prep: pack W into tf32 fragment layout; zero the merge counters.
// ---------------------------------------------------------------------------
__global__ __launch_bounds__(256) void prep_w(
    const float* __restrict__ Wq, const float* __restrict__ Wk)
{
    if (blockIdx.x == 0 && threadIdx.x < BSZ * 32)
        g_cnt[threadIdx.x] = 0;
    #pragma unroll
    for (int h = 0; h < 2; h++) {
        int idx  = h * 32768 + blockIdx.x * 256 + threadIdx.x;
        int sel  = idx >> 15;
        int rem  = idx & 32767;
        int k8g  = rem >> 8;
        int n    = (rem >> 2) & 63;
        int qd   = rem & 3;
        int c    = k8g * 8 + qd;
        const float* src = sel ? Wk : Wq;
        float w0 = src[(size_t)n * DMODEL + c];
        float w1 = src[(size_t)n * DMODEL + c + 4];
        g_Wp[idx] = make_float2(__uint_as_float(f2tf(w0)),
                                __uint_as_float(f2tf(w1)));
    }
}

// ---------------------------------------------------------------------------
// Fused projection (single tf32): [Q|K] = x @ [Wq|Wk]^T   (unchanged from R8)
// ---------------------------------------------------------------------------
__global__ __launch_bounds__(256, 3) void proj_mma(const float* __restrict__ x)
{
    __shared__ float4 XsP[16][17];

    const int tid  = threadIdx.x;
    const int lane = tid & 31;
    const int w    = tid >> 5;
    const int gid  = lane >> 2;
    const int qd   = lane & 3;
    const int mw   = w & 1;
    const int nw   = w >> 1;
    const int row0 = blockIdx.x * 32;

    const int lr    = tid >> 3;
    const int lsg   = (tid & 7) * 4;
    const int lk8   = lsg >> 3;
    const int lhalf = (lsg >> 2) & 1;
    const int lp    = (lr & 7) + ((lr >> 4) << 3);
    const int lhi   = (lr >> 3) & 1;
    const int slotA = lhalf * 2 + lhi;

    const int sel = nw >> 1;
    const float2* wp = &g_Wp[((size_t)sel * 128 * 64 + (nw & 1) * 32 + gid) * 4 + qd];

    float acc[4][4] = {};
    float4 px = *(const float4*)&x[(size_t)(row0 + lr) * DMODEL + lsg];

    for (int kc = 0; kc < DMODEL; kc += 32) {
        const int k8g0 = kc >> 3;

        float2 bf[4][4];
        #pragma unroll
        for (int k8 = 0; k8 < 4; k8++)
            #pragma unroll
            for (int nt = 0; nt < 4; nt++)
                bf[k8][nt] = wp[((size_t)(k8g0 + k8) * 64 + nt * 8) * 4];

        __syncthreads();

        {
            float vx[4] = {px.x, px.y, px.z, px.w};
            #pragma unroll
            for (int j = 0; j < 4; j++)
                ((float*)&XsP[lp][lk8 * 4 + j])[slotA] =
                    __uint_as_float(f2tf(vx[j]));
        }

        int kn = (kc + 32 < DMODEL) ? kc + 32 : 0;
        px = *(const float4*)&x[(size_t)(row0 + lr) * DMODEL + kn + lsg];

        __syncthreads();

        #pragma unroll
        for (int k8 = 0; k8 < 4; k8++) {
            float4 af = XsP[mw * 8 + gid][k8 * 4 + qd];
            unsigned a0 = fbits(af.x), a1 = fbits(af.y);
            unsigned a2 = fbits(af.z), a3 = fbits(af.w);
            #pragma unroll
            for (int nt = 0; nt < 4; nt++)
                mma_tf32(acc[nt], a0, a1, a2, a3,
                         fbits(bf[k8][nt].x), fbits(bf[k8][nt].y));
        }
    }

    float* outp = (nw < 2) ? g_Q : g_K;
    const int r = row0 + mw * 16 + gid;
    #pragma unroll
    for (int nt = 0; nt < 4; nt++) {
        int cb = (nw & 1) * 32 + nt * 8 + 2 * qd;
        *(float2*)&outp[(size_t)r * DHEAD + cb] =
            make_float2(acc[nt][0], acc[nt][1]);
        *(float2*)&outp[(size_t)(r + 8) * DHEAD + cb] =
            make_float2(acc[nt][2], acc[nt][3]);
    }
}

// ---------------------------------------------------------------------------
// Flash attention, split-KV (chunks <= 6 tiles), LDSM fragments, in-kernel
// last-CTA merge. grid = (102, BSZ), 128 threads. V == K (reference bug).
// ---------------------------------------------------------------------------
__global__ __launch_bounds__(128, 3) void attn_mma(float* __restrict__ out)
{
    __shared__ __align__(16) float Ks[2][64][68];
    __shared__ __align__(16) float Ps[64][68];
    __shared__ int s_last;

    const int b   = blockIdx.y;
    const int cid = blockIdx.x;

    // decode (qt, ck): nch(qt) = ceil((qt+1)/6)
    int qt = 0, ck = cid;
    for (;;) { int n = (qt + 6) / 6; if (ck < n) break; ck -= n; qt++; }
    const int ntile = qt + 1;
    const int nch   = (qt + 6) / 6;
    const int bse   = ntile / nch;
    const int ext   = ntile % nch;
    const int nkv   = bse + (ck < ext ? 1 : 0);
    const int kv0   = ck * bse + (ck < ext ? ck : ext);

    const int tid  = threadIdx.x;
    const int lane = tid & 31;
    const int w    = tid >> 5;
    const int gid  = lane >> 2;
    const int qd   = lane & 3;
    const int r0l  = w * 16 + gid;

    const int qrow0 = b * TLEN + qt * 64;
    const uint32_t ks_u32 = (uint32_t)__cvta_generic_to_shared(&Ks[0][0][0]);
    const uint32_t ps_u32 = (uint32_t)__cvta_generic_to_shared(&Ps[0][0]);

    // LDSM lane->address coords
    const int s_row  = ((lane >> 4) << 3) + (lane & 7);   // S-loop: within ntp band
    const int s_col  = ((lane >> 3) & 1) * 4;
    const int pa_row = w * 16 + ((lane >> 3) & 1) * 8 + (lane & 7);  // PV A from Ps
    const int pa_col = (lane >> 4) * 4;

    // --- cp.async K-tile issue (16B x 8 per thread = 16KB tile) ---
    auto issue_tile = [&](int buf, int ktg) {
        const float* kb = &g_K[(size_t)(b * TLEN + ktg * 64) * DHEAD];
        #pragma unroll
        for (int i = 0; i < 8; i++) {
            int lin = i * 128 + tid;
            int row = lin >> 4, sg = (lin & 15) * 4;
            cp16(ks_u32 + (uint32_t)(((buf * 64 + row) * 68 + sg) * 4),
                 kb + row * 64 + sg);
        }
        cpcommit();
    };

    issue_tile(0, kv0);
    if (nkv > 1) issue_tile(1, kv0 + 1);

    // Q fragments (held in regs whole kernel)
    unsigned aq[8][4];
    {
        const float* qp = &g_Q[(size_t)(qrow0 + r0l) * DHEAD];
        #pragma unroll
        for (int k8 = 0; k8 < 8; k8++) {
            int c = k8 * 8 + qd;
            aq[k8][0] = f2tf(qp[c]);
            aq[k8][1] = f2tf(qp[8 * DHEAD + c]);
            aq[k8][2] = f2tf(qp[c + 4]);
            aq[k8][3] = f2tf(qp[8 * DHEAD + c + 4]);
        }
    }

    if (nkv > 1) cpwait<1>(); else cpwait<0>();
    __syncthreads();

    float o[8][4] = {};
    float mr0 = -1e30f, mr1 = -1e30f, lr0 = 0.f, lr1 = 0.f;
    const float scale = 0.03125f;  // 1/sqrt(d_model=1024)

    #pragma unroll 1
    for (int kt = 0; kt < nkv; kt++) {
        const int cur = kt & 1;
        const int ktg = kv0 + kt;

        // ---- S = Q @ K^T : B-frags via ldmatrix.x4 ----
        float s[8][4] = {};
        #pragma unroll
        for (int k8 = 0; k8 < 8; k8++) {
            #pragma unroll
            for (int ntp = 0; ntp < 4; ntp++) {
                uint32_t b0, b1, b2, b3;
                uint32_t a = ks_u32 +
                    (uint32_t)(((cur * 64 + ntp * 16 + s_row) * 68 + k8 * 8 + s_col) * 4);
                ldsm4(b0, b1, b2, b3, a);
                mma_tf32(s[2*ntp],     aq[k8][0], aq[k8][1], aq[k8][2], aq[k8][3], b0, b1);
                mma_tf32(s[2*ntp + 1], aq[k8][0], aq[k8][1], aq[k8][2], aq[k8][3], b2, b3);
            }
        }
        #pragma unroll
        for (int nt = 0; nt < 8; nt++)
            #pragma unroll
            for (int j = 0; j < 4; j++)
                s[nt][j] *= scale;

        if (ktg == qt) {   // diagonal tile: causal mask
            const int ra = qt * 64 + r0l, rb = ra + 8;
            #pragma unroll
            for (int nt = 0; nt < 8; nt++) {
                int cb = ktg * 64 + nt * 8 + 2 * qd;
                if (cb     > ra) s[nt][0] = -1e30f;
                if (cb + 1 > ra) s[nt][1] = -1e30f;
                if (cb     > rb) s[nt][2] = -1e30f;
                if (cb + 1 > rb) s[nt][3] = -1e30f;
            }
        }

        // ---- warp-local softmax (rows r0l, r0l+8) ----
        float tm0 = -1e30f, tm1 = -1e30f;
        #pragma unroll
        for (int nt = 0; nt < 8; nt++) {
            tm0 = fmaxf(tm0, fmaxf(s[nt][0], s[nt][1]));
            tm1 = fmaxf(tm1, fmaxf(s[nt][2], s[nt][3]));
        }
        tm0 = fmaxf(tm0, __shfl_xor_sync(0xffffffffu, tm0, 1));
        tm0 = fmaxf(tm0, __shfl_xor_sync(0xffffffffu, tm0, 2));
        tm1 = fmaxf(tm1, __shfl_xor_sync(0xffffffffu, tm1, 1));
        tm1 = fmaxf(tm1, __shfl_xor_sync(0xffffffffu, tm1, 2));

        float mn0 = fmaxf(mr0, tm0), mn1 = fmaxf(mr1, tm1);
        float corr0 = __expf(mr0 - mn0), corr1 = __expf(mr1 - mn1);
        mr0 = mn0; mr1 = mn1;

        float ps0 = 0.f, ps1 = 0.f;
        #pragma unroll
        for (int nt = 0; nt < 8; nt++) {
            float p0 = __expf(s[nt][0] - mn0);
            float p1 = __expf(s[nt][1] - mn0);
            float p2 = __expf(s[nt][2] - mn1);
            float p3 = __expf(s[nt][3] - mn1);
            ps0 += p0 + p1;
            ps1 += p2 + p3;
            int cb = nt * 8 + 2 * qd;
            *(float2*)&Ps[r0l][cb] =
                make_float2(__uint_as_float(f2tf(p0)), __uint_as_float(f2tf(p1)));
            *(float2*)&Ps[r0l + 8][cb] =
                make_float2(__uint_as_float(f2tf(p2)), __uint_as_float(f2tf(p3)));
        }
        ps0 += __shfl_xor_sync(0xffffffffu, ps0, 1);
        ps0 += __shfl_xor_sync(0xffffffffu, ps0, 2);
        ps1 += __shfl_xor_sync(0xffffffffu, ps1, 1);
        ps1 += __shfl_xor_sync(0xffffffffu, ps1, 2);
        lr0 = lr0 * corr0 + ps0;
        lr1 = lr1 * corr1 + ps1;

        #pragma unroll
        for (int nt = 0; nt < 8; nt++) {
            o[nt][0] *= corr0; o[nt][1] *= corr0;
            o[nt][2] *= corr1; o[nt][3] *= corr1;
        }

        __syncwarp();   // Ps rows are warp-private

        // ---- O += P @ V  (V == K tile): A-frags via ldmatrix.x4 ----
        #pragma unroll
        for (int k8 = 0; k8 < 8; k8++) {
            int c = k8 * 8 + qd;
            uint32_t a0, a1, a2, a3;
            uint32_t pa = ps_u32 + (uint32_t)((pa_row * 68 + k8 * 8 + pa_col) * 4);
            ldsm4(a0, a1, a2, a3, pa);
            #pragma unroll
            for (int nt = 0; nt < 8; nt++) {
                int d = nt * 8 + gid;
                unsigned b0 = fbits(Ks[cur][c][d]);
                unsigned b1 = fbits(Ks[cur][c + 4][d]);
                mma_tf32(o[nt], a0, a1, a2, a3, b0, b1);
            }
        }

        // ---- pipeline: refill cur with tile kt+2, ensure kt+1 ready ----
        if (kt + 1 < nkv) {
            __syncthreads();
            if (kt + 2 < nkv) { issue_tile(cur, kv0 + kt + 2); cpwait<1>(); }
            else              { cpwait<0>(); }
            __syncthreads();
        }
    }

    // ---- epilogue ----
    if (nch == 1) {
        float inv0 = 1.0f / lr0, inv1 = 1.0f / lr1;
        #pragma unroll
        for (int nt = 0; nt < 8; nt++) {
            int cb = nt * 8 + 2 * qd;
            *(float2*)&out[(size_t)(qrow0 + r0l) * DHEAD + cb] =
                make_float2(o[nt][0] * inv0, o[nt][1] * inv0);
            *(float2*)&out[(size_t)(qrow0 + r0l + 8) * DHEAD + cb] =
                make_float2(o[nt][2] * inv1, o[nt][3] * inv1);
        }
        return;
    }

    // write partial (unnormalized O, m, l)
    const int pb  = (b * 32 + qt) * 6;
    const int pid = pb + ck;
    {
        float* pp = &g_part[(size_t)pid * 4096];
        #pragma unroll
        for (int nt = 0; nt < 8; nt++) {
            int cb = nt * 8 + 2 * qd;
            *(float2*)&pp[(size_t)r0l * 64 + cb]       = make_float2(o[nt][0], o[nt][1]);
            *(float2*)&pp[(size_t)(r0l + 8) * 64 + cb] = make_float2(o[nt][2], o[nt][3]);
        }
        if (qd == 0) {
            g_pm[pid * 64 + r0l]     = mr0;
            g_pm[pid * 64 + r0l + 8] = mr1;
            g_pl[pid * 64 + r0l]     = lr0;
            g_pl[pid * 64 + r0l + 8] = lr1;
        }
    }
    __threadfence();
    if (tid == 0) {
        int old = atomicAdd(&g_cnt[b * 32 + qt], 1);
        s_last = (old == nch - 1) ? 1 : 0;
    }
    __syncthreads();
    if (!s_last) return;
    __threadfence();   // acquire: other chunks' partials now visible

    // merge all nch partials (this CTA is the last one for this qt)
    float mA = -1e30f, mB = -1e30f;
    for (int i = 0; i < nch; i++) {
        mA = fmaxf(mA, g_pm[(pb + i) * 64 + r0l]);
        mB = fmaxf(mB, g_pm[(pb + i) * 64 + r0l + 8]);
    }
    float lA = 0.f, lB = 0.f;
    float accA[8][2] = {}, accB[8][2] = {};
    for (int i = 0; i < nch; i++) {
        float wA = __expf(g_pm[(pb + i) * 64 + r0l]     - mA);
        float wB = __expf(g_pm[(pb + i) * 64 + r0l + 8] - mB);
        lA += wA * g_pl[(pb + i) * 64 + r0l];
        lB += wB * g_pl[(pb + i) * 64 + r0l + 8];
        const float* qp2 = &g_part[(size_t)(pb + i) * 4096];
        #pragma unroll
        for (int nt = 0; nt < 8; nt++) {
            int cb = nt * 8 + 2 * qd;
            float2 vA = *(const float2*)&qp2[(size_t)r0l * 64 + cb];
            float2 vB = *(const float2*)&qp2[(size_t)(r0l + 8) * 64 + cb];
            accA[nt][0] += wA * vA.x; accA[nt][1] += wA * vA.y;
            accB[nt][0] += wB * vB.x; accB[nt][1] += wB * vB.y;
        }
    }
    float ivA = 1.0f / lA, ivB = 1.0f / lB;
    #pragma unroll
    for (int nt = 0; nt < 8; nt++) {
        int cb = nt * 8 + 2 * qd;
        *(float2*)&out[(size_t)(qrow0 + r0l) * DHEAD + cb] =
            make_float2(accA[nt][0] * ivA, accA[nt][1] * ivA);
        *(float2*)&out[(size_t)(qrow0 + r0l + 8) * DHEAD + cb] =
            make_float2(accB[nt][0] * ivB, accB[nt][1] * ivB);
    }
}

extern "C" void kernel_launch(void* const* d_in, const int* in_sizes, int n_in,
                              void* d_out, int out_size)
{
    const float* x  = (const float*)d_in[0];
    const float* Wq = (const float*)d_in[1];
    const float* Wk = (const float*)d_in[2];
    // d_in[3] (W_V) intentionally unused: reference computes V with W_K.
    float* out = (float*)d_out;

    prep_w  <<<128, 256>>>(Wq, Wk);
    proj_mma<<<256, 256>>>(x);
    attn_mma<<<dim3(102, BSZ), 128>>>(out);
}